// round 10
// baseline (speedup 1.0000x reference)
#include <cuda_runtime.h>
#include <cuda_bf16.h>
#include <cstdint>
#include <math.h>

#define B_ROWS 8192
#define S_DIM  268
#define SP_DIM 320          // padded K for state/W0 (multiple of 32)
#define H_DIM  1024
#define A_DIM  256
#define NF_PAD 512          // padded row count for Wf (268 -> 512)

#if defined(__CUDA_ARCH__) && defined(__CUDA_ARCH_FEAT_SM103_ALL)
#define TC_ENABLED 1
#else
#define TC_ENABLED 0
#endif

#define STG_STRIDE 132      // floats; %4==0 (float4 aligned)

// CTA tile: 128 rows x 256 cols, K chunk 32 (SW64, 64B rows)
#define A_TILE_BYTES 8192    // 128 rows x 64B
#define B_TILE_BYTES 16384   // 256 rows x 64B
#define STAGE_BYTES (2 * A_TILE_BYTES + 2 * B_TILE_BYTES)   // 48KB
#define NSTAGES 2
#define SMEM_TOTAL (NSTAGES * STAGE_BYTES)   // 98304 -> 2 CTAs/SM

// ---------------- scratch (static device memory only) ----------------
__device__ float g_beff[H_DIM];

__device__ __nv_bfloat16 g_state_hi[B_ROWS * SP_DIM];
__device__ __nv_bfloat16 g_state_lo[B_ROWS * SP_DIM];
__device__ __nv_bfloat16 g_w0_hi[H_DIM * SP_DIM];
__device__ __nv_bfloat16 g_w0_lo[H_DIM * SP_DIM];
__device__ __nv_bfloat16 g_h_hi[B_ROWS * H_DIM];
__device__ __nv_bfloat16 g_h_lo[B_ROWS * H_DIM];
__device__ __nv_bfloat16 g_u_hi[B_ROWS * H_DIM];
__device__ __nv_bfloat16 g_u_lo[B_ROWS * H_DIM];
__device__ __nv_bfloat16 g_r1_hi[8 * H_DIM * H_DIM];
__device__ __nv_bfloat16 g_r1_lo[8 * H_DIM * H_DIM];
__device__ __nv_bfloat16 g_r2_hi[8 * H_DIM * H_DIM];
__device__ __nv_bfloat16 g_r2_lo[8 * H_DIM * H_DIM];
__device__ __nv_bfloat16 g_wf_hi[NF_PAD * H_DIM];
__device__ __nv_bfloat16 g_wf_lo[NF_PAD * H_DIM];
__device__ __nv_bfloat16 g_tain_hi[A_DIM * A_DIM];
__device__ __nv_bfloat16 g_tain_lo[A_DIM * A_DIM];
__device__ __nv_bfloat16 g_taout_hi[A_DIM * A_DIM];
__device__ __nv_bfloat16 g_taout_lo[A_DIM * A_DIM];
__device__ __nv_bfloat16 g_v2_hi[B_ROWS * A_DIM];
__device__ __nv_bfloat16 g_v2_lo[B_ROWS * A_DIM];

// ---------------- ptx helpers ----------------
__device__ __forceinline__ uint32_t smem_u32(const void* p) {
    uint32_t a;
    asm("{ .reg .u64 t; cvta.to.shared.u64 t, %1; cvt.u32.u64 %0, t; }" : "=r"(a) : "l"(p));
    return a;
}
__device__ __forceinline__ bool elect_one() {
    uint32_t pred;
    asm volatile("{\n\t.reg .pred p;\n\telect.sync _|p, 0xFFFFFFFF;\n\tselp.b32 %0, 1, 0, p;\n\t}"
                 : "=r"(pred));
    return pred != 0;
}
__device__ __forceinline__ void mbar_init(uint32_t addr, uint32_t cnt) {
    asm volatile("mbarrier.init.shared.b64 [%0], %1;" :: "r"(addr), "r"(cnt) : "memory");
}
__device__ __forceinline__ void mbar_wait(uint32_t addr, uint32_t parity) {
    asm volatile(
        "{\n\t.reg .pred P;\n"
        "WL_%=:\n\t"
        "mbarrier.try_wait.parity.acquire.cta.shared::cta.b64 P, [%0], %1, 0x989680;\n\t"
        "@P bra WD_%=;\n\t"
        "bra WL_%=;\n"
        "WD_%=:\n\t}"
        :: "r"(addr), "r"(parity) : "memory");
}
__device__ __forceinline__ void fence_proxy_async_cta() {
    asm volatile("fence.proxy.async.shared::cta;" ::: "memory");
}
__device__ __forceinline__ void cp_async16(uint32_t dst, const void* src) {
    asm volatile("cp.async.cg.shared.global [%0], [%1], 16;"
                 :: "r"(dst), "l"(src) : "memory");
}
__device__ __forceinline__ void cp_commit() {
    asm volatile("cp.async.commit_group;" ::: "memory");
}
__device__ __forceinline__ void cp_wait0() {
    asm volatile("cp.async.wait_group 0;" ::: "memory");
}
__device__ __forceinline__ void cp_wait1() {
    asm volatile("cp.async.wait_group 1;" ::: "memory");
}

#if TC_ENABLED
__device__ __forceinline__ void tc_alloc(uint32_t smem_dst, uint32_t ncols) {
    asm volatile("tcgen05.alloc.cta_group::1.sync.aligned.shared::cta.b32 [%0], %1;"
                 :: "r"(smem_dst), "r"(ncols) : "memory");
    asm volatile("tcgen05.relinquish_alloc_permit.cta_group::1.sync.aligned;");
}
__device__ __forceinline__ void tc_dealloc(uint32_t tmem, uint32_t ncols) {
    asm volatile("tcgen05.dealloc.cta_group::1.sync.aligned.b32 %0, %1;"
                 :: "r"(tmem), "r"(ncols));
}
__device__ __forceinline__ void tc_commit(uint32_t mbar) {
    asm volatile("tcgen05.commit.cta_group::1.mbarrier::arrive::one.shared::cluster.b64 [%0];"
                 :: "r"(mbar) : "memory");
}
__device__ __forceinline__ void tc_mma_f16_ss(uint32_t d, uint64_t ad, uint64_t bd,
                                              uint32_t idesc, uint32_t en) {
    asm volatile(
        "{\n\t.reg .pred p;\n\tsetp.ne.u32 p, %4, 0;\n\t"
        "tcgen05.mma.cta_group::1.kind::f16 [%0], %1, %2, %3, p;\n\t}"
        :: "r"(d), "l"(ad), "l"(bd), "r"(idesc), "r"(en) : "memory");
}
__device__ __forceinline__ void tc_fence_after() {
    asm volatile("tcgen05.fence::after_thread_sync;" ::: "memory");
}
__device__ __forceinline__ void tc_fence_before() {
    asm volatile("tcgen05.fence::before_thread_sync;" ::: "memory");
}
__device__ __forceinline__ void tc_ld32_nw(uint32_t* regs, uint32_t addr) {
    asm volatile(
        "tcgen05.ld.sync.aligned.32x32b.x32.b32 "
        "{%0, %1, %2, %3, %4, %5, %6, %7, %8, %9, %10, %11, %12, %13, %14, %15, "
        " %16, %17, %18, %19, %20, %21, %22, %23, %24, %25, %26, %27, %28, %29, %30, %31}, [%32];"
        : "=r"(regs[0]),  "=r"(regs[1]),  "=r"(regs[2]),  "=r"(regs[3]),
          "=r"(regs[4]),  "=r"(regs[5]),  "=r"(regs[6]),  "=r"(regs[7]),
          "=r"(regs[8]),  "=r"(regs[9]),  "=r"(regs[10]), "=r"(regs[11]),
          "=r"(regs[12]), "=r"(regs[13]), "=r"(regs[14]), "=r"(regs[15]),
          "=r"(regs[16]), "=r"(regs[17]), "=r"(regs[18]), "=r"(regs[19]),
          "=r"(regs[20]), "=r"(regs[21]), "=r"(regs[22]), "=r"(regs[23]),
          "=r"(regs[24]), "=r"(regs[25]), "=r"(regs[26]), "=r"(regs[27]),
          "=r"(regs[28]), "=r"(regs[29]), "=r"(regs[30]), "=r"(regs[31])
        : "r"(addr));
}
__device__ __forceinline__ void tc_wait_ld() {
    asm volatile("tcgen05.wait::ld.sync.aligned;" ::: "memory");
}
#endif

// SW64 K-major descriptor: layout=4, SBO=32 (512B atom), LBO=1
static constexpr uint64_t DESC_BASE_SW64 =
    (4ull << 61) | (1ull << 46) | (32ull << 32) | (1ull << 16);
__device__ __forceinline__ uint64_t make_desc64(uint32_t a) {
    return DESC_BASE_SW64 | (uint64_t)((a >> 4) & 0x3FFF);
}

// idesc: F32 accum, BF16 a/b, N=256, M=128
#define TC_IDESC (0x490u | (32u << 17) | (8u << 24))

// ---------------- fused prep: beff + all hi/lo conversions (ONE launch) -------
__device__ __forceinline__ void conv4_store(float4 v, __nv_bfloat16* hi,
                                            __nv_bfloat16* lo, size_t e) {
    __nv_bfloat16 h0 = __float2bfloat16(v.x), h1 = __float2bfloat16(v.y);
    __nv_bfloat16 h2 = __float2bfloat16(v.z), h3 = __float2bfloat16(v.w);
    __nv_bfloat162* hp = (__nv_bfloat162*)(hi + e);
    hp[0] = __nv_bfloat162(h0, h1);
    hp[1] = __nv_bfloat162(h2, h3);
    __nv_bfloat162* lp = (__nv_bfloat162*)(lo + e);
    lp[0] = __nv_bfloat162(__float2bfloat16(v.x - __bfloat162float(h0)),
                           __float2bfloat16(v.y - __bfloat162float(h1)));
    lp[1] = __nv_bfloat162(__float2bfloat16(v.z - __bfloat162float(h2)),
                           __float2bfloat16(v.w - __bfloat162float(h3)));
}

#define N_STATE (B_ROWS * SP_DIM / 4)
#define N_W0    (H_DIM * SP_DIM / 4)
#define N_R     (8 * H_DIM * H_DIM / 4)
#define N_WF    (NF_PAD * H_DIM / 4)
#define N_TA    (A_DIM * A_DIM / 4)
#define PREP_TOTAL (N_STATE + N_W0 + 2 * N_R + N_WF + 2 * N_TA + H_DIM)

__global__ void prep_all(const float* __restrict__ t, const float* __restrict__ b0,
                         const float* __restrict__ state, const float* __restrict__ W0,
                         const float* __restrict__ r1, const float* __restrict__ r2,
                         const float* __restrict__ wf,
                         const float* __restrict__ tain, const float* __restrict__ taout) {
    int i = blockIdx.x * blockDim.x + threadIdx.x;
    if (i < N_STATE) {
        int e = i * 4;
        int r = e / SP_DIM, c0 = e - r * SP_DIM;
        float4 v;
        float* vp = (float*)&v;
#pragma unroll
        for (int k = 0; k < 4; k++) {
            int c = c0 + k;
            vp[k] = (c < S_DIM) ? state[(size_t)r * S_DIM + c] : 0.0f;
        }
        conv4_store(v, g_state_hi, g_state_lo, (size_t)e);
        return;
    }
    i -= N_STATE;
    if (i < N_W0) {
        int e = i * 4;
        int r = e / SP_DIM, c0 = e - r * SP_DIM;
        float4 v;
        float* vp = (float*)&v;
#pragma unroll
        for (int k = 0; k < 4; k++) {
            int c = c0 + k;
            vp[k] = (c < S_DIM) ? W0[(size_t)r * 270 + c] : 0.0f;
        }
        conv4_store(v, g_w0_hi, g_w0_lo, (size_t)e);
        return;
    }
    i -= N_W0;
    if (i < N_R) { conv4_store(((const float4*)r1)[i], g_r1_hi, g_r1_lo, (size_t)i * 4); return; }
    i -= N_R;
    if (i < N_R) { conv4_store(((const float4*)r2)[i], g_r2_hi, g_r2_lo, (size_t)i * 4); return; }
    i -= N_R;
    if (i < N_WF) {
        int e = i * 4;
        int r = e / H_DIM;
        float4 v = (r < S_DIM) ? ((const float4*)wf)[i] : make_float4(0.f, 0.f, 0.f, 0.f);
        conv4_store(v, g_wf_hi, g_wf_lo, (size_t)e);
        return;
    }
    i -= N_WF;
    if (i < N_TA) { conv4_store(((const float4*)tain)[i], g_tain_hi, g_tain_lo, (size_t)i * 4); return; }
    i -= N_TA;
    if (i < N_TA) { conv4_store(((const float4*)taout)[i], g_taout_hi, g_taout_lo, (size_t)i * 4); return; }
    i -= N_TA;
    if (i < H_DIM) {
        float ang = t[0] * (float)(2.0 * M_PI / 24.0);
        float s, c;
        sincosf(ang, &s, &c);
        g_beff[i] = b0[i] + s * W0[i * 270 + 268] + c * W0[i * 270 + 269];
    }
}

// ---------------- GEMM: C = epi(A @ B^T + bias) ----------------
// CTA tile 128x256 (2 CTAs/SM); A/B hi+lo bf16, K chunk 32 (SW64), 2-stage
// cp.async pipeline, BAR.SYNC chunk rendezvous.
// MODE 0: v ; 1: relu(v) ; 2: tanh(v) ; 3: tanh((addhi+addlo)+v) ; 4: C += 0.1*(v - sub)
template <int MODE, bool WF32, bool WHL>
__global__ void __launch_bounds__(256, 2)
tc_gemm(const __nv_bfloat16* __restrict__ Ahi, const __nv_bfloat16* __restrict__ Alo, int lda,
        const __nv_bfloat16* __restrict__ Bhi, const __nv_bfloat16* __restrict__ Blo, int ldb,
        const float* __restrict__ bias,
        const __nv_bfloat16* __restrict__ addhi, const __nv_bfloat16* __restrict__ addlo, int ldadd,
        const float* __restrict__ sub, int ldsub,
        float* __restrict__ C, int ldc,
        __nv_bfloat16* __restrict__ Chi, __nv_bfloat16* __restrict__ Clo, int ldchl,
        int Nreal, int K)
{
#if TC_ENABLED
    extern __shared__ __align__(1024) char smem[];
    __shared__ __align__(8) uint64_t s_done[NSTAGES];
    __shared__ uint32_t s_tmemptr;

    const int tid = threadIdx.x;
    const int wid = tid >> 5;
    const int lid = tid & 31;
    const int block_row = blockIdx.y * 128;
    const int block_col = blockIdx.x * 256;

    uint32_t dn[NSTAGES];
#pragma unroll
    for (int s = 0; s < NSTAGES; s++) dn[s] = smem_u32(&s_done[s]);
    if (tid == 0) {
#pragma unroll
        for (int s = 0; s < NSTAGES; s++) mbar_init(dn[s], 1);
    }
    if (wid == 0) tc_alloc(smem_u32(&s_tmemptr), 256u);
    __syncthreads();
    const uint32_t tmem = s_tmemptr;
    const uint32_t sbase = smem_u32(smem);

    // stage layout: [Ahi 8K][Alo 8K][Bhi 16K][Blo 16K]
    auto load_tileA = [&](uint32_t sb, const __nv_bfloat16* src, int k0) {
#pragma unroll
        for (int i = 0; i < 2; i++) {
            int idx = tid + i * 256;            // 0..511
            int r = idx >> 2, seg = idx & 3;
            const void* g = src + (size_t)(block_row + r) * lda + k0 + seg * 8;
            uint32_t off = r * 64 + seg * 16;
            off ^= (off >> 3) & 0x30;
            cp_async16(sb + off, g);
        }
    };
    auto load_tileB = [&](uint32_t sb, const __nv_bfloat16* src, int k0) {
#pragma unroll
        for (int i = 0; i < 4; i++) {
            int idx = tid + i * 256;            // 0..1023
            int r = idx >> 2, seg = idx & 3;
            const void* g = src + (size_t)(block_col + r) * ldb + k0 + seg * 8;
            uint32_t off = r * 64 + seg * 16;
            off ^= (off >> 3) & 0x30;
            cp_async16(sb + off, g);
        }
    };
    auto load_stage = [&](int s, int c) {
        int k0 = c * 32;
        uint32_t b = sbase + (uint32_t)s * STAGE_BYTES;
        load_tileA(b, Ahi, k0);
        load_tileA(b + A_TILE_BYTES, Alo, k0);
        load_tileB(b + 2 * A_TILE_BYTES, Bhi, k0);
        load_tileB(b + 2 * A_TILE_BYTES + B_TILE_BYTES, Blo, k0);
        cp_commit();
    };

    const int nchunks = K / 32;
    load_stage(0, 0);
    load_stage(1, 1);

    uint32_t phd[NSTAGES] = {0, 0};
    for (int c = 0; c < nchunks; c++) {
        const int s = c % NSTAGES;
        if (c + 1 < nchunks) cp_wait1(); else cp_wait0();   // chunk c landed
        __syncthreads();
        if (wid == 0) {
            fence_proxy_async_cta();
            if (elect_one()) {
                uint32_t b = sbase + (uint32_t)s * STAGE_BYTES;
                uint64_t dA0 = make_desc64(b);
                uint64_t dA1 = make_desc64(b + A_TILE_BYTES);
                uint64_t dB0 = make_desc64(b + 2 * A_TILE_BYTES);
                uint64_t dB1 = make_desc64(b + 2 * A_TILE_BYTES + B_TILE_BYTES);
#pragma unroll
                for (int ks = 0; ks < 2; ks++) {
                    uint64_t o = (uint64_t)(ks * 2);    // 32B per K=16 step
                    uint32_t en0 = (c > 0 || ks > 0) ? 1u : 0u;
                    tc_mma_f16_ss(tmem, dA0 + o, dB0 + o, TC_IDESC, en0);
                    tc_mma_f16_ss(tmem, dA0 + o, dB1 + o, TC_IDESC, 1);
                    tc_mma_f16_ss(tmem, dA1 + o, dB0 + o, TC_IDESC, 1);
                }
                tc_commit(dn[s]);
            }
        }
        if (c + 2 < nchunks) {
            const int s2 = (c + 2) % NSTAGES;   // == s: reuse needs MMA(c) done
            mbar_wait(dn[s2], phd[s2]);
            phd[s2] ^= 1;
            load_stage(s2, c + 2);
        }
    }
    {
        const int sl = (nchunks - 1) % NSTAGES;
        mbar_wait(dn[sl], phd[sl]);   // in-order commits => all MMAs done
    }
    tc_fence_after();

    // ---- epilogue: two 128-col halves through 128x132 staging ----
    float* stage = (float*)smem;
    const int sp = wid & 3;                  // subpartition (rows sp*32..+31)
    const int cg = wid >> 2;                 // col group within half (cg*64)
    const int ccol = (tid & 31) * 4;         // phase-B col offset within half
    const int rgrp = tid >> 5;               // 8 groups x 16 rows

    for (int half = 0; half < 2; half++) {
        // phase A: TMEM -> staging
        const int r = sp * 32 + lid;
#pragma unroll
        for (int b = 0; b < 2; b++) {
            uint32_t regs[32];
            tc_ld32_nw(regs, tmem + half * 128 + cg * 64 + b * 32);
            tc_wait_ld();
#pragma unroll
            for (int j = 0; j < 32; j++)
                stage[r * STG_STRIDE + cg * 64 + b * 32 + j] = __uint_as_float(regs[j]);
        }
        __syncthreads();

        // phase B: coalesced global I/O
        const int gcol = block_col + half * 128 + ccol;
        const bool colok = (gcol < Nreal);     // Nreal % 4 == 0
        for (int rr = 0; rr < 16; rr++) {
            int r2 = rgrp * 16 + rr;
            int grow = block_row + r2;
            float4 v = *(const float4*)&stage[r2 * STG_STRIDE + ccol];
            if (colok) {
                float4 bb = *(const float4*)(bias + gcol);
                float f[4] = {v.x + bb.x, v.y + bb.y, v.z + bb.z, v.w + bb.w};
                if (MODE == 1) {
#pragma unroll
                    for (int k = 0; k < 4; k++) f[k] = fmaxf(f[k], 0.0f);
                } else if (MODE == 2) {
#pragma unroll
                    for (int k = 0; k < 4; k++) f[k] = tanhf(f[k]);
                } else if (MODE == 3) {
                    const __nv_bfloat162* ah = (const __nv_bfloat162*)(addhi + (size_t)grow * ldadd + gcol);
                    const __nv_bfloat162* al = (const __nv_bfloat162*)(addlo + (size_t)grow * ldadd + gcol);
                    float2 h01 = __bfloat1622float2(ah[0]), h23 = __bfloat1622float2(ah[1]);
                    float2 l01 = __bfloat1622float2(al[0]), l23 = __bfloat1622float2(al[1]);
                    f[0] = tanhf(f[0] + h01.x + l01.x);
                    f[1] = tanhf(f[1] + h01.y + l01.y);
                    f[2] = tanhf(f[2] + h23.x + l23.x);
                    f[3] = tanhf(f[3] + h23.y + l23.y);
                } else if (MODE == 4) {
                    float4 s4 = *(const float4*)(sub + (size_t)grow * ldsub + gcol);
                    float4 c4 = *(const float4*)(C + (size_t)grow * ldc + gcol);
                    f[0] = c4.x + 0.1f * (f[0] - s4.x);
                    f[1] = c4.y + 0.1f * (f[1] - s4.y);
                    f[2] = c4.z + 0.1f * (f[2] - s4.z);
                    f[3] = c4.w + 0.1f * (f[3] - s4.w);
                }
                if (WF32 || MODE == 4) {
                    float4 o4 = {f[0], f[1], f[2], f[3]};
                    *(float4*)(C + (size_t)grow * ldc + gcol) = o4;
                }
                if (WHL) {
                    __nv_bfloat16 h0 = __float2bfloat16(f[0]), h1 = __float2bfloat16(f[1]);
                    __nv_bfloat16 h2 = __float2bfloat16(f[2]), h3 = __float2bfloat16(f[3]);
                    __nv_bfloat162* hp = (__nv_bfloat162*)(Chi + (size_t)grow * ldchl + gcol);
                    hp[0] = __nv_bfloat162(h0, h1);
                    hp[1] = __nv_bfloat162(h2, h3);
                    __nv_bfloat162* lp = (__nv_bfloat162*)(Clo + (size_t)grow * ldchl + gcol);
                    lp[0] = __nv_bfloat162(__float2bfloat16(f[0] - __bfloat162float(h0)),
                                           __float2bfloat16(f[1] - __bfloat162float(h1)));
                    lp[1] = __nv_bfloat162(__float2bfloat16(f[2] - __bfloat162float(h2)),
                                           __float2bfloat16(f[3] - __bfloat162float(h3)));
                }
            }
        }
        __syncthreads();   // staging reused by next half
    }
    tc_fence_before();
    if (wid == 0) tc_dealloc(tmem, 256u);
#else
    // scalar fallback for the non-sm_103a PTX pass (never selected at runtime)
    const int tid = threadIdx.x;
    if (tid >= 128) return;
    const int block_row = blockIdx.y * 128;
    const int block_col = blockIdx.x * 256;
    const int row = block_row + tid;
    for (int j = 0; j < 256; j++) {
        int col = block_col + j;
        if (col >= Nreal) continue;
        float acc = 0.0f;
        for (int k = 0; k < K; k++) {
            float a = __bfloat162float(Ahi[(size_t)row * lda + k]) +
                      __bfloat162float(Alo[(size_t)row * lda + k]);
            float w = __bfloat162float(Bhi[(size_t)col * ldb + k]) +
                      __bfloat162float(Blo[(size_t)col * ldb + k]);
            acc = fmaf(a, w, acc);
        }
        float v = acc + bias[col];
        float f;
        if (MODE == 0) f = v;
        else if (MODE == 1) f = fmaxf(v, 0.0f);
        else if (MODE == 2) f = tanhf(v);
        else if (MODE == 3) {
            float av = __bfloat162float(addhi[(size_t)row * ldadd + col]) +
                       __bfloat162float(addlo[(size_t)row * ldadd + col]);
            f = tanhf(av + v);
        } else {
            f = C[(size_t)row * ldc + col] + 0.1f * (v - sub[(size_t)row * ldsub + col]);
        }
        if (WF32 || MODE == 4) C[(size_t)row * ldc + col] = f;
        if (WHL) {
            __nv_bfloat16 h = __float2bfloat16(f);
            Chi[(size_t)row * ldchl + col] = h;
            Clo[(size_t)row * ldchl + col] = __float2bfloat16(f - __bfloat162float(h));
        }
    }
#endif
}

// ---------------- tiny per-row loc path ----------------
__global__ void loc_final_kernel(const float* __restrict__ state,
                                 const float* __restrict__ lp_in_w, const float* __restrict__ lp_in_b,
                                 const float* __restrict__ lp_out_w, const float* __restrict__ lp_out_b,
                                 const float* __restrict__ loc_proj_w, const float* __restrict__ loc_proj_b,
                                 const float* __restrict__ loc_back_w, const float* __restrict__ loc_back_b,
                                 float* __restrict__ out)
{
    int m = blockIdx.x * blockDim.x + threadIdx.x;
    if (m >= B_ROWS) return;
    float loc[8];
#pragma unroll
    for (int z = 0; z < 8; z++) loc[z] = state[(size_t)m * S_DIM + A_DIM + z];
    float locp[4];
#pragma unroll
    for (int e = 0; e < 4; e++) {
        float s = loc_proj_b[e];
#pragma unroll
        for (int z = 0; z < 8; z++) s = fmaf(loc_proj_w[e * 8 + z], loc[z], s);
        locp[e] = s;
    }
    float v[4];
#pragma unroll
    for (int e = 0; e < 4; e++) {
        float s = lp_in_b[8 + e];
#pragma unroll
        for (int j = 0; j < 4; j++) s = fmaf(lp_in_w[(8 + e) * 4 + j], locp[j], s);
        v[e] = s;
    }
    float enh[4];
#pragma unroll
    for (int e = 0; e < 4; e++) {
        float s = lp_out_b[e];
#pragma unroll
        for (int j = 0; j < 4; j++) s = fmaf(lp_out_w[e * 4 + j], v[j], s);
        enh[e] = s - locp[e];
    }
#pragma unroll
    for (int z = 0; z < 8; z++) {
        float s = loc_back_b[z];
#pragma unroll
        for (int e = 0; e < 4; e++) s = fmaf(loc_back_w[z * 4 + e], enh[e], s);
        out[(size_t)m * S_DIM + A_DIM + z] += 0.1f * s;
    }
}

// ---------------- host ----------------
template <int MODE, bool WF32, bool WHL>
static void launch_tc(const __nv_bfloat16* Ahi, const __nv_bfloat16* Alo, int lda,
                      const __nv_bfloat16* Bhi, const __nv_bfloat16* Blo, int ldb,
                      const float* bias,
                      const __nv_bfloat16* addhi, const __nv_bfloat16* addlo, int ldadd,
                      const float* sub, int ldsub,
                      float* C, int ldc,
                      __nv_bfloat16* Chi, __nv_bfloat16* Clo, int ldchl,
                      int Npad, int Nreal, int K)
{
    static bool attr_done = false;
    if (!attr_done) {
        cudaFuncSetAttribute(tc_gemm<MODE, WF32, WHL>,
                             cudaFuncAttributeMaxDynamicSharedMemorySize, SMEM_TOTAL);
        attr_done = true;
    }
    dim3 grid(Npad / 256, B_ROWS / 128);
    tc_gemm<MODE, WF32, WHL><<<grid, 256, SMEM_TOTAL>>>(
        Ahi, Alo, lda, Bhi, Blo, ldb, bias, addhi, addlo, ldadd, sub, ldsub,
        C, ldc, Chi, Clo, ldchl, Nreal, K);
}

extern "C" void kernel_launch(void* const* d_in, const int* in_sizes, int n_in,
                              void* d_out, int out_size)
{
    const float* t          = (const float*)d_in[0];
    const float* state      = (const float*)d_in[1];
    const float* W0         = (const float*)d_in[2];
    const float* b0         = (const float*)d_in[3];
    const float* res_W1     = (const float*)d_in[4];
    const float* res_b1     = (const float*)d_in[5];
    const float* res_W2     = (const float*)d_in[6];
    const float* res_b2     = (const float*)d_in[7];
    const float* Wf         = (const float*)d_in[8];
    const float* bf         = (const float*)d_in[9];
    const float* lp_in_w    = (const float*)d_in[10];
    const float* lp_in_b    = (const float*)d_in[11];
    const float* lp_out_w   = (const float*)d_in[12];
    const float* lp_out_b   = (const float*)d_in[13];
    const float* ta_in_w    = (const float*)d_in[14];
    const float* ta_in_b    = (const float*)d_in[15];
    const float* ta_out_w   = (const float*)d_in[16];
    const float* ta_out_b   = (const float*)d_in[17];
    const float* loc_proj_w = (const float*)d_in[18];
    const float* loc_proj_b = (const float*)d_in[19];
    const float* loc_back_w = (const float*)d_in[20];
    const float* loc_back_b = (const float*)d_in[21];
    float* out = (float*)d_out;

    float* pbeff;
    cudaGetSymbolAddress((void**)&pbeff, g_beff);
    __nv_bfloat16 *p_st_hi, *p_st_lo, *p_w0_hi, *p_w0_lo, *p_h_hi, *p_h_lo,
        *p_u_hi, *p_u_lo, *p_r1_hi, *p_r1_lo, *p_r2_hi, *p_r2_lo,
        *p_wf_hi, *p_wf_lo, *p_tain_hi, *p_tain_lo, *p_taout_hi, *p_taout_lo,
        *p_v2_hi, *p_v2_lo;
    cudaGetSymbolAddress((void**)&p_st_hi, g_state_hi);
    cudaGetSymbolAddress((void**)&p_st_lo, g_state_lo);
    cudaGetSymbolAddress((void**)&p_w0_hi, g_w0_hi);
    cudaGetSymbolAddress((void**)&p_w0_lo, g_w0_lo);
    cudaGetSymbolAddress((void**)&p_h_hi, g_h_hi);
    cudaGetSymbolAddress((void**)&p_h_lo, g_h_lo);
    cudaGetSymbolAddress((void**)&p_u_hi, g_u_hi);
    cudaGetSymbolAddress((void**)&p_u_lo, g_u_lo);
    cudaGetSymbolAddress((void**)&p_r1_hi, g_r1_hi);
    cudaGetSymbolAddress((void**)&p_r1_lo, g_r1_lo);
    cudaGetSymbolAddress((void**)&p_r2_hi, g_r2_hi);
    cudaGetSymbolAddress((void**)&p_r2_lo, g_r2_lo);
    cudaGetSymbolAddress((void**)&p_wf_hi, g_wf_hi);
    cudaGetSymbolAddress((void**)&p_wf_lo, g_wf_lo);
    cudaGetSymbolAddress((void**)&p_tain_hi, g_tain_hi);
    cudaGetSymbolAddress((void**)&p_tain_lo, g_tain_lo);
    cudaGetSymbolAddress((void**)&p_taout_hi, g_taout_hi);
    cudaGetSymbolAddress((void**)&p_taout_lo, g_taout_lo);
    cudaGetSymbolAddress((void**)&p_v2_hi, g_v2_hi);
    cudaGetSymbolAddress((void**)&p_v2_lo, g_v2_lo);

    // ---- ONE fused prep launch ----
    prep_all<<<(PREP_TOTAL + 255) / 256, 256>>>(
        t, b0, state, W0, res_W1, res_W2, Wf,
        ta_in_w + (size_t)2 * A_DIM * A_DIM, ta_out_w);

    // ---- GEMM 0: h = relu(state @ W0^T + beff) -> h hi/lo ----
    launch_tc<1, false, true>(p_st_hi, p_st_lo, SP_DIM, p_w0_hi, p_w0_lo, SP_DIM,
                              pbeff, nullptr, nullptr, 0, nullptr, 0,
                              nullptr, 0, p_h_hi, p_h_lo, H_DIM, H_DIM, H_DIM, SP_DIM);

    // ---- 8 residual blocks ----
    for (int r = 0; r < 8; r++) {
        const __nv_bfloat16* W1h = p_r1_hi + (size_t)r * H_DIM * H_DIM;
        const __nv_bfloat16* W1l = p_r1_lo + (size_t)r * H_DIM * H_DIM;
        const __nv_bfloat16* W2h = p_r2_hi + (size_t)r * H_DIM * H_DIM;
        const __nv_bfloat16* W2l = p_r2_lo + (size_t)r * H_DIM * H_DIM;
        const float* b1 = res_b1 + (size_t)r * H_DIM;
        const float* b2 = res_b2 + (size_t)r * H_DIM;
        // u = tanh(h @ W1^T + b1) -> u_hl
        launch_tc<2, false, true>(p_h_hi, p_h_lo, H_DIM, W1h, W1l, H_DIM,
                                  b1, nullptr, nullptr, 0, nullptr, 0,
                                  nullptr, 0, p_u_hi, p_u_lo, H_DIM, H_DIM, H_DIM, H_DIM);
        // h = tanh(h + u @ W2^T + b2) -> h hi/lo
        launch_tc<3, false, true>(p_u_hi, p_u_lo, H_DIM, W2h, W2l, H_DIM,
                                  b2, p_h_hi, p_h_lo, H_DIM, nullptr, 0,
                                  nullptr, 0, p_h_hi, p_h_lo, H_DIM, H_DIM, H_DIM, H_DIM);
    }

    // ---- core = h @ Wf^T + bf -> out (Npad=512, Nreal=268) ----
    launch_tc<0, true, false>(p_h_hi, p_h_lo, H_DIM, p_wf_hi, p_wf_lo, H_DIM,
                              bf, nullptr, nullptr, 0, nullptr, 0,
                              out, S_DIM, nullptr, nullptr, 0, NF_PAD, S_DIM, H_DIM);

    // ---- v2 = state[:, :256] @ ta_in_w[2A:]^T + b -> v2_hl ----
    launch_tc<0, false, true>(p_st_hi, p_st_lo, SP_DIM, p_tain_hi, p_tain_lo, A_DIM,
                              ta_in_b + 2 * A_DIM, nullptr, nullptr, 0, nullptr, 0,
                              nullptr, 0, p_v2_hi, p_v2_lo, A_DIM, A_DIM, A_DIM, A_DIM);

    // ---- out[:, :256] += 0.1 * (v2 @ ta_out_w^T + b - h_part) ----
    launch_tc<4, true, false>(p_v2_hi, p_v2_lo, A_DIM, p_taout_hi, p_taout_lo, A_DIM,
                              ta_out_b, nullptr, nullptr, 0, state, S_DIM,
                              out, S_DIM, nullptr, nullptr, 0, A_DIM, A_DIM, A_DIM);

    // ---- loc path ----
    loc_final_kernel<<<(B_ROWS + 255) / 256, 256>>>(
        state, lp_in_w, lp_in_b, lp_out_w, lp_out_b,
        loc_proj_w, loc_proj_b, loc_back_w, loc_back_b, out);
}

// round 11
// speedup vs baseline: 1.1433x; 1.1433x over previous
#include <cuda_runtime.h>
#include <cuda_bf16.h>
#include <cstdint>
#include <math.h>

#define B_ROWS 8192
#define S_DIM  268
#define SP_DIM 320
#define H_DIM  1024
#define A_DIM  256
#define NF_PAD 512

#if defined(__CUDA_ARCH__) && defined(__CUDA_ARCH_FEAT_SM103_ALL)
#define TC_ENABLED 1
#else
#define TC_ENABLED 0
#endif

#define STG_STRIDE 260      // floats; %4==0 (float4 aligned)

#define TILE_BYTES 16384    // one operand tile: 256 rows x 64B (K=32 bf16, SW64)
#define STAGE_BYTES (4 * TILE_BYTES)
#define NSTAGES 3
#define SMEM_TOTAL (NSTAGES * STAGE_BYTES)   // 196608

// ---------------- scratch ----------------
__device__ float g_beff[H_DIM];
__device__ __nv_bfloat16 g_state_hi[B_ROWS * SP_DIM];
__device__ __nv_bfloat16 g_state_lo[B_ROWS * SP_DIM];
__device__ __nv_bfloat16 g_w0_hi[H_DIM * SP_DIM];
__device__ __nv_bfloat16 g_w0_lo[H_DIM * SP_DIM];
__device__ __nv_bfloat16 g_h_hi[B_ROWS * H_DIM];
__device__ __nv_bfloat16 g_h_lo[B_ROWS * H_DIM];
__device__ __nv_bfloat16 g_u_hi[B_ROWS * H_DIM];
__device__ __nv_bfloat16 g_u_lo[B_ROWS * H_DIM];
__device__ __nv_bfloat16 g_r1_hi[8 * H_DIM * H_DIM];
__device__ __nv_bfloat16 g_r1_lo[8 * H_DIM * H_DIM];
__device__ __nv_bfloat16 g_r2_hi[8 * H_DIM * H_DIM];
__device__ __nv_bfloat16 g_r2_lo[8 * H_DIM * H_DIM];
__device__ __nv_bfloat16 g_wf_hi[NF_PAD * H_DIM];
__device__ __nv_bfloat16 g_wf_lo[NF_PAD * H_DIM];
__device__ __nv_bfloat16 g_tain_hi[A_DIM * A_DIM];
__device__ __nv_bfloat16 g_tain_lo[A_DIM * A_DIM];
__device__ __nv_bfloat16 g_taout_hi[A_DIM * A_DIM];
__device__ __nv_bfloat16 g_taout_lo[A_DIM * A_DIM];
__device__ __nv_bfloat16 g_v2_hi[B_ROWS * A_DIM];
__device__ __nv_bfloat16 g_v2_lo[B_ROWS * A_DIM];

// ---------------- ptx helpers ----------------
__device__ __forceinline__ uint32_t smem_u32(const void* p) {
    uint32_t a;
    asm("{ .reg .u64 t; cvta.to.shared.u64 t, %1; cvt.u32.u64 %0, t; }" : "=r"(a) : "l"(p));
    return a;
}
__device__ __forceinline__ bool elect_one() {
    uint32_t pred;
    asm volatile("{\n\t.reg .pred p;\n\telect.sync _|p, 0xFFFFFFFF;\n\tselp.b32 %0, 1, 0, p;\n\t}"
                 : "=r"(pred));
    return pred != 0;
}
__device__ __forceinline__ void mbar_init(uint32_t addr, uint32_t cnt) {
    asm volatile("mbarrier.init.shared.b64 [%0], %1;" :: "r"(addr), "r"(cnt) : "memory");
}
__device__ __forceinline__ void mbar_wait(uint32_t addr, uint32_t parity) {
    asm volatile(
        "{\n\t.reg .pred P;\n"
        "WL_%=:\n\t"
        "mbarrier.try_wait.parity.acquire.cta.shared::cta.b64 P, [%0], %1, 0x989680;\n\t"
        "@P bra WD_%=;\n\t"
        "bra WL_%=;\n"
        "WD_%=:\n\t}"
        :: "r"(addr), "r"(parity) : "memory");
}
__device__ __forceinline__ void fence_proxy_async_cta() {
    asm volatile("fence.proxy.async.shared::cta;" ::: "memory");
}
__device__ __forceinline__ void cp_async16(uint32_t dst, const void* src) {
    asm volatile("cp.async.cg.shared.global [%0], [%1], 16;"
                 :: "r"(dst), "l"(src) : "memory");
}
__device__ __forceinline__ void cp_mbar_arrive(uint32_t mbar) {
    asm volatile("cp.async.mbarrier.arrive.noinc.shared::cta.b64 [%0];"
                 :: "r"(mbar) : "memory");
}

#if TC_ENABLED
__device__ __forceinline__ void tc_alloc(uint32_t smem_dst, uint32_t ncols) {
    asm volatile("tcgen05.alloc.cta_group::1.sync.aligned.shared::cta.b32 [%0], %1;"
                 :: "r"(smem_dst), "r"(ncols) : "memory");
    asm volatile("tcgen05.relinquish_alloc_permit.cta_group::1.sync.aligned;");
}
__device__ __forceinline__ void tc_dealloc(uint32_t tmem, uint32_t ncols) {
    asm volatile("tcgen05.dealloc.cta_group::1.sync.aligned.b32 %0, %1;"
                 :: "r"(tmem), "r"(ncols));
}
__device__ __forceinline__ void tc_commit(uint32_t mbar) {
    asm volatile("tcgen05.commit.cta_group::1.mbarrier::arrive::one.shared::cluster.b64 [%0];"
                 :: "r"(mbar) : "memory");
}
__device__ __forceinline__ void tc_mma_f16_ss(uint32_t d, uint64_t ad, uint64_t bd,
                                              uint32_t idesc, uint32_t en) {
    asm volatile(
        "{\n\t.reg .pred p;\n\tsetp.ne.u32 p, %4, 0;\n\t"
        "tcgen05.mma.cta_group::1.kind::f16 [%0], %1, %2, %3, p;\n\t}"
        :: "r"(d), "l"(ad), "l"(bd), "r"(idesc), "r"(en) : "memory");
}
__device__ __forceinline__ void tc_fence_after() {
    asm volatile("tcgen05.fence::after_thread_sync;" ::: "memory");
}
__device__ __forceinline__ void tc_fence_before() {
    asm volatile("tcgen05.fence::before_thread_sync;" ::: "memory");
}
__device__ __forceinline__ void tc_ld32_nw(uint32_t* regs, uint32_t addr) {
    asm volatile(
        "tcgen05.ld.sync.aligned.32x32b.x32.b32 "
        "{%0, %1, %2, %3, %4, %5, %6, %7, %8, %9, %10, %11, %12, %13, %14, %15, "
        " %16, %17, %18, %19, %20, %21, %22, %23, %24, %25, %26, %27, %28, %29, %30, %31}, [%32];"
        : "=r"(regs[0]),  "=r"(regs[1]),  "=r"(regs[2]),  "=r"(regs[3]),
          "=r"(regs[4]),  "=r"(regs[5]),  "=r"(regs[6]),  "=r"(regs[7]),
          "=r"(regs[8]),  "=r"(regs[9]),  "=r"(regs[10]), "=r"(regs[11]),
          "=r"(regs[12]), "=r"(regs[13]), "=r"(regs[14]), "=r"(regs[15]),
          "=r"(regs[16]), "=r"(regs[17]), "=r"(regs[18]), "=r"(regs[19]),
          "=r"(regs[20]), "=r"(regs[21]), "=r"(regs[22]), "=r"(regs[23]),
          "=r"(regs[24]), "=r"(regs[25]), "=r"(regs[26]), "=r"(regs[27]),
          "=r"(regs[28]), "=r"(regs[29]), "=r"(regs[30]), "=r"(regs[31])
        : "r"(addr));
}
__device__ __forceinline__ void tc_wait_ld() {
    asm volatile("tcgen05.wait::ld.sync.aligned;" ::: "memory");
}
#endif

// SW64 K-major descriptor: layout=4, SBO=32, LBO=1
static constexpr uint64_t DESC_BASE_SW64 =
    (4ull << 61) | (1ull << 46) | (32ull << 32) | (1ull << 16);
__device__ __forceinline__ uint64_t make_desc64(uint32_t a) {
    return DESC_BASE_SW64 | (uint64_t)((a >> 4) & 0x3FFF);
}

// idesc: F32 accum, BF16 a/b, N=256, M=128
#define TC_IDESC (0x490u | (32u << 17) | (8u << 24))

// ---------------- fused prep ----------------
__device__ __forceinline__ void conv4_store(float4 v, __nv_bfloat16* hi,
                                            __nv_bfloat16* lo, size_t e) {
    __nv_bfloat16 h0 = __float2bfloat16(v.x), h1 = __float2bfloat16(v.y);
    __nv_bfloat16 h2 = __float2bfloat16(v.z), h3 = __float2bfloat16(v.w);
    __nv_bfloat162* hp = (__nv_bfloat162*)(hi + e);
    hp[0] = __nv_bfloat162(h0, h1);
    hp[1] = __nv_bfloat162(h2, h3);
    __nv_bfloat162* lp = (__nv_bfloat162*)(lo + e);
    lp[0] = __nv_bfloat162(__float2bfloat16(v.x - __bfloat162float(h0)),
                           __float2bfloat16(v.y - __bfloat162float(h1)));
    lp[1] = __nv_bfloat162(__float2bfloat16(v.z - __bfloat162float(h2)),
                           __float2bfloat16(v.w - __bfloat162float(h3)));
}

#define N_STATE (B_ROWS * SP_DIM / 4)
#define N_W0    (H_DIM * SP_DIM / 4)
#define N_R     (8 * H_DIM * H_DIM / 4)
#define N_WF    (NF_PAD * H_DIM / 4)
#define N_TA    (A_DIM * A_DIM / 4)
#define PREP_TOTAL (N_STATE + N_W0 + 2 * N_R + N_WF + 2 * N_TA + H_DIM)

__global__ void prep_all(const float* __restrict__ t, const float* __restrict__ b0,
                         const float* __restrict__ state, const float* __restrict__ W0,
                         const float* __restrict__ r1, const float* __restrict__ r2,
                         const float* __restrict__ wf,
                         const float* __restrict__ tain, const float* __restrict__ taout) {
    int i = blockIdx.x * blockDim.x + threadIdx.x;
    if (i < N_STATE) {
        int e = i * 4;
        int r = e / SP_DIM, c0 = e - r * SP_DIM;
        float4 v;
        float* vp = (float*)&v;
#pragma unroll
        for (int k = 0; k < 4; k++) {
            int c = c0 + k;
            vp[k] = (c < S_DIM) ? state[(size_t)r * S_DIM + c] : 0.0f;
        }
        conv4_store(v, g_state_hi, g_state_lo, (size_t)e);
        return;
    }
    i -= N_STATE;
    if (i < N_W0) {
        int e = i * 4;
        int r = e / SP_DIM, c0 = e - r * SP_DIM;
        float4 v;
        float* vp = (float*)&v;
#pragma unroll
        for (int k = 0; k < 4; k++) {
            int c = c0 + k;
            vp[k] = (c < S_DIM) ? W0[(size_t)r * 270 + c] : 0.0f;
        }
        conv4_store(v, g_w0_hi, g_w0_lo, (size_t)e);
        return;
    }
    i -= N_W0;
    if (i < N_R) { conv4_store(((const float4*)r1)[i], g_r1_hi, g_r1_lo, (size_t)i * 4); return; }
    i -= N_R;
    if (i < N_R) { conv4_store(((const float4*)r2)[i], g_r2_hi, g_r2_lo, (size_t)i * 4); return; }
    i -= N_R;
    if (i < N_WF) {
        int e = i * 4;
        int r = e / H_DIM;
        float4 v = (r < S_DIM) ? ((const float4*)wf)[i] : make_float4(0.f, 0.f, 0.f, 0.f);
        conv4_store(v, g_wf_hi, g_wf_lo, (size_t)e);
        return;
    }
    i -= N_WF;
    if (i < N_TA) { conv4_store(((const float4*)tain)[i], g_tain_hi, g_tain_lo, (size_t)i * 4); return; }
    i -= N_TA;
    if (i < N_TA) { conv4_store(((const float4*)taout)[i], g_taout_hi, g_taout_lo, (size_t)i * 4); return; }
    i -= N_TA;
    if (i < H_DIM) {
        float ang = t[0] * (float)(2.0 * M_PI / 24.0);
        float s, c;
        sincosf(ang, &s, &c);
        g_beff[i] = b0[i] + s * W0[i * 270 + 268] + c * W0[i * 270 + 269];
    }
}

// ---------------- GEMM: C = epi(A @ B^T + bias) ----------------
// 256x256 tile, warp-specialized: warps 4-7 produce (cp.async + mbarrier arrive),
// warp 0 elected thread consumes (MMA issue + tcgen05.commit). No CTA barrier
// in the mainloop; stages recycle purely on mbarrier phases.
template <int MODE, bool WF32, bool WHL>
__global__ void __launch_bounds__(256, 1)
tc_gemm(const __nv_bfloat16* __restrict__ Ahi, const __nv_bfloat16* __restrict__ Alo, int lda,
        const __nv_bfloat16* __restrict__ Bhi, const __nv_bfloat16* __restrict__ Blo, int ldb,
        const float* __restrict__ bias,
        const __nv_bfloat16* __restrict__ addhi, const __nv_bfloat16* __restrict__ addlo, int ldadd,
        const float* __restrict__ sub, int ldsub,
        float* __restrict__ C, int ldc,
        __nv_bfloat16* __restrict__ Chi, __nv_bfloat16* __restrict__ Clo, int ldchl,
        int Nreal, int K)
{
#if TC_ENABLED
    extern __shared__ __align__(1024) char smem[];
    __shared__ __align__(8) uint64_t s_full[NSTAGES];   // 128 producer arrivals
    __shared__ __align__(8) uint64_t s_empty[NSTAGES];  // 1 arrival (tc commit)
    __shared__ uint32_t s_tmemptr;

    const int tid = threadIdx.x;
    const int wid = tid >> 5;
    const int lid = tid & 31;
    const int block_row = blockIdx.y * 256;
    const int block_col = blockIdx.x * 256;

    uint32_t fb[NSTAGES], eb[NSTAGES];
#pragma unroll
    for (int s = 0; s < NSTAGES; s++) {
        fb[s] = smem_u32(&s_full[s]);
        eb[s] = smem_u32(&s_empty[s]);
    }
    if (tid == 0) {
#pragma unroll
        for (int s = 0; s < NSTAGES; s++) {
            mbar_init(fb[s], 128);
            mbar_init(eb[s], 1);
        }
    }
    if (wid == 0) tc_alloc(smem_u32(&s_tmemptr), 512u);
    __syncthreads();
    const uint32_t tmem = s_tmemptr;
    const uint32_t sbase = smem_u32(smem);
    const int nchunks = K / 32;

    if (wid >= 4) {
        // ---------------- producer: 128 threads ----------------
        const int ptid = tid - 128;
        uint32_t pe[NSTAGES] = {0, 0, 0};
        for (int c = 0; c < nchunks; c++) {
            const int s = c % NSTAGES;
            if (c >= NSTAGES) {
                mbar_wait(eb[s], pe[s]);
                pe[s] ^= 1;
            }
            const int k0 = c * 32;
            const uint32_t b = sbase + (uint32_t)s * STAGE_BYTES;
            // 4 operand tiles: Ahi, Alo (row base block_row), Bhi, Blo (block_col)
#pragma unroll
            for (int op = 0; op < 4; op++) {
                const __nv_bfloat16* src = (op == 0) ? Ahi : (op == 1) ? Alo
                                          : (op == 2) ? Bhi : Blo;
                const int row0 = (op < 2) ? block_row : block_col;
                const int ld = (op < 2) ? lda : ldb;
                uint32_t sb = b + (uint32_t)op * TILE_BYTES;
#pragma unroll
                for (int i = 0; i < 8; i++) {
                    int idx = ptid + i * 128;           // 0..1023
                    int r = idx >> 2, seg = idx & 3;
                    const void* g = src + (size_t)(row0 + r) * ld + k0 + seg * 8;
                    uint32_t off = r * 64 + seg * 16;
                    off ^= (off >> 3) & 0x30;
                    cp_async16(sb + off, g);
                }
            }
            cp_mbar_arrive(fb[s]);   // arrives when this thread's cp.asyncs land
        }
    } else if (wid == 0 && elect_one()) {
        // ---------------- consumer: single MMA issuer ----------------
        uint32_t pf[NSTAGES] = {0, 0, 0};
        for (int c = 0; c < nchunks; c++) {
            const int s = c % NSTAGES;
            mbar_wait(fb[s], pf[s]);
            pf[s] ^= 1;
            fence_proxy_async_cta();
            uint32_t b = sbase + (uint32_t)s * STAGE_BYTES;
            uint64_t dAh = make_desc64(b);
            uint64_t dAl = make_desc64(b + TILE_BYTES);
            uint64_t dBh = make_desc64(b + 2 * TILE_BYTES);
            uint64_t dBl = make_desc64(b + 3 * TILE_BYTES);
#pragma unroll
            for (int ks = 0; ks < 2; ks++) {
                uint64_t o = (uint64_t)(ks * 2);    // 32B per K=16 step
#pragma unroll
                for (int half = 0; half < 2; half++) {
                    uint32_t d = tmem + half * 256;
                    uint64_t ha = (uint64_t)(half * 512);  // 128 rows * 64B / 16
                    uint32_t en0 = (c > 0 || ks > 0) ? 1u : 0u;
                    tc_mma_f16_ss(d, dAh + ha + o, dBh + o, TC_IDESC, en0);
                    tc_mma_f16_ss(d, dAh + ha + o, dBl + o, TC_IDESC, 1);
                    tc_mma_f16_ss(d, dAl + ha + o, dBh + o, TC_IDESC, 1);
                }
            }
            tc_commit(eb[s]);
        }
        // wait final commit (all earlier commits are ordered before it)
        const int sl = (nchunks - 1) % NSTAGES;
        const int uses = (nchunks - 1) / NSTAGES + 1;
        mbar_wait(eb[sl], (uint32_t)((uses - 1) & 1));
    }
    __syncthreads();          // gates epilogue on the issuer's final wait
    tc_fence_after();

    // ---- epilogue (R9-proven): two M halves; 8 warps column-split ----
    float* stage = (float*)smem;
    const int wq = wid & 3;
    const int colh = (wid >= 4) ? 128 : 0;
    const int cgrp = tid & 63;
    const int rgrp = tid >> 6;
    const int gcol = block_col + cgrp * 4;
    const bool colok = (gcol < Nreal);

    for (int half = 0; half < 2; half++) {
        const int r = wq * 32 + lid;
#pragma unroll
        for (int b = 0; b < 4; b += 2) {
            uint32_t regs0[32], regs1[32];
            tc_ld32_nw(regs0, tmem + half * 256 + colh + b * 32);
            tc_ld32_nw(regs1, tmem + half * 256 + colh + (b + 1) * 32);
            tc_wait_ld();
#pragma unroll
            for (int j = 0; j < 32; j++) {
                stage[r * STG_STRIDE + colh + b * 32 + j] = __uint_as_float(regs0[j]);
                stage[r * STG_STRIDE + colh + (b + 1) * 32 + j] = __uint_as_float(regs1[j]);
            }
        }
        __syncthreads();

        for (int rr = 0; rr < 32; rr++) {
            int r2 = rgrp * 32 + rr;
            int grow = block_row + half * 128 + r2;
            float4 v = *(const float4*)&stage[r2 * STG_STRIDE + cgrp * 4];
            if (colok) {
                float4 bb = *(const float4*)(bias + gcol);
                float f[4] = {v.x + bb.x, v.y + bb.y, v.z + bb.z, v.w + bb.w};
                if (MODE == 1) {
#pragma unroll
                    for (int k = 0; k < 4; k++) f[k] = fmaxf(f[k], 0.0f);
                } else if (MODE == 2) {
#pragma unroll
                    for (int k = 0; k < 4; k++) f[k] = tanhf(f[k]);
                } else if (MODE == 3) {
                    const __nv_bfloat162* ah = (const __nv_bfloat162*)(addhi + (size_t)grow * ldadd + gcol);
                    const __nv_bfloat162* al = (const __nv_bfloat162*)(addlo + (size_t)grow * ldadd + gcol);
                    float2 h01 = __bfloat1622float2(ah[0]), h23 = __bfloat1622float2(ah[1]);
                    float2 l01 = __bfloat1622float2(al[0]), l23 = __bfloat1622float2(al[1]);
                    f[0] = tanhf(f[0] + h01.x + l01.x);
                    f[1] = tanhf(f[1] + h01.y + l01.y);
                    f[2] = tanhf(f[2] + h23.x + l23.x);
                    f[3] = tanhf(f[3] + h23.y + l23.y);
                } else if (MODE == 4) {
                    float4 s4 = *(const float4*)(sub + (size_t)grow * ldsub + gcol);
                    float4 c4 = *(const float4*)(C + (size_t)grow * ldc + gcol);
                    f[0] = c4.x + 0.1f * (f[0] - s4.x);
                    f[1] = c4.y + 0.1f * (f[1] - s4.y);
                    f[2] = c4.z + 0.1f * (f[2] - s4.z);
                    f[3] = c4.w + 0.1f * (f[3] - s4.w);
                }
                if (WF32 || MODE == 4) {
                    float4 o4 = {f[0], f[1], f[2], f[3]};
                    *(float4*)(C + (size_t)grow * ldc + gcol) = o4;
                }
                if (WHL) {
                    __nv_bfloat16 h0 = __float2bfloat16(f[0]), h1 = __float2bfloat16(f[1]);
                    __nv_bfloat16 h2 = __float2bfloat16(f[2]), h3 = __float2bfloat16(f[3]);
                    __nv_bfloat162* hp = (__nv_bfloat162*)(Chi + (size_t)grow * ldchl + gcol);
                    hp[0] = __nv_bfloat162(h0, h1);
                    hp[1] = __nv_bfloat162(h2, h3);
                    __nv_bfloat162* lp = (__nv_bfloat162*)(Clo + (size_t)grow * ldchl + gcol);
                    lp[0] = __nv_bfloat162(__float2bfloat16(f[0] - __bfloat162float(h0)),
                                           __float2bfloat16(f[1] - __bfloat162float(h1)));
                    lp[1] = __nv_bfloat162(__float2bfloat16(f[2] - __bfloat162float(h2)),
                                           __float2bfloat16(f[3] - __bfloat162float(h3)));
                }
            }
        }
        __syncthreads();
    }
    tc_fence_before();
    if (wid == 0) tc_dealloc(tmem, 512u);
#else
    // scalar fallback for the non-sm_103a PTX pass (never selected at runtime)
    const int tid = threadIdx.x;
    const int block_row = blockIdx.y * 256;
    const int block_col = blockIdx.x * 256;
    const int row = block_row + tid;
    for (int j = 0; j < 256; j++) {
        int col = block_col + j;
        if (col >= Nreal) continue;
        float acc = 0.0f;
        for (int k = 0; k < K; k++) {
            float a = __bfloat162float(Ahi[(size_t)row * lda + k]) +
                      __bfloat162float(Alo[(size_t)row * lda + k]);
            float w = __bfloat162float(Bhi[(size_t)col * ldb + k]) +
                      __bfloat162float(Blo[(size_t)col * ldb + k]);
            acc = fmaf(a, w, acc);
        }
        float v = acc + bias[col];
        float f;
        if (MODE == 0) f = v;
        else if (MODE == 1) f = fmaxf(v, 0.0f);
        else if (MODE == 2) f = tanhf(v);
        else if (MODE == 3) {
            float av = __bfloat162float(addhi[(size_t)row * ldadd + col]) +
                       __bfloat162float(addlo[(size_t)row * ldadd + col]);
            f = tanhf(av + v);
        } else {
            f = C[(size_t)row * ldc + col] + 0.1f * (v - sub[(size_t)row * ldsub + col]);
        }
        if (WF32 || MODE == 4) C[(size_t)row * ldc + col] = f;
        if (WHL) {
            __nv_bfloat16 h = __float2bfloat16(f);
            Chi[(size_t)row * ldchl + col] = h;
            Clo[(size_t)row * ldchl + col] = __float2bfloat16(f - __bfloat162float(h));
        }
    }
#endif
}

// ---------------- tiny per-row loc path ----------------
__global__ void loc_final_kernel(const float* __restrict__ state,
                                 const float* __restrict__ lp_in_w, const float* __restrict__ lp_in_b,
                                 const float* __restrict__ lp_out_w, const float* __restrict__ lp_out_b,
                                 const float* __restrict__ loc_proj_w, const float* __restrict__ loc_proj_b,
                                 const float* __restrict__ loc_back_w, const float* __restrict__ loc_back_b,
                                 float* __restrict__ out)
{
    int m = blockIdx.x * blockDim.x + threadIdx.x;
    if (m >= B_ROWS) return;
    float loc[8];
#pragma unroll
    for (int z = 0; z < 8; z++) loc[z] = state[(size_t)m * S_DIM + A_DIM + z];
    float locp[4];
#pragma unroll
    for (int e = 0; e < 4; e++) {
        float s = loc_proj_b[e];
#pragma unroll
        for (int z = 0; z < 8; z++) s = fmaf(loc_proj_w[e * 8 + z], loc[z], s);
        locp[e] = s;
    }
    float v[4];
#pragma unroll
    for (int e = 0; e < 4; e++) {
        float s = lp_in_b[8 + e];
#pragma unroll
        for (int j = 0; j < 4; j++) s = fmaf(lp_in_w[(8 + e) * 4 + j], locp[j], s);
        v[e] = s;
    }
    float enh[4];
#pragma unroll
    for (int e = 0; e < 4; e++) {
        float s = lp_out_b[e];
#pragma unroll
        for (int j = 0; j < 4; j++) s = fmaf(lp_out_w[e * 4 + j], v[j], s);
        enh[e] = s - locp[e];
    }
#pragma unroll
    for (int z = 0; z < 8; z++) {
        float s = loc_back_b[z];
#pragma unroll
        for (int e = 0; e < 4; e++) s = fmaf(loc_back_w[z * 4 + e], enh[e], s);
        out[(size_t)m * S_DIM + A_DIM + z] += 0.1f * s;
    }
}

// ---------------- host ----------------
template <int MODE, bool WF32, bool WHL>
static void launch_tc(const __nv_bfloat16* Ahi, const __nv_bfloat16* Alo, int lda,
                      const __nv_bfloat16* Bhi, const __nv_bfloat16* Blo, int ldb,
                      const float* bias,
                      const __nv_bfloat16* addhi, const __nv_bfloat16* addlo, int ldadd,
                      const float* sub, int ldsub,
                      float* C, int ldc,
                      __nv_bfloat16* Chi, __nv_bfloat16* Clo, int ldchl,
                      int Npad, int Nreal, int K)
{
    static bool attr_done = false;
    if (!attr_done) {
        cudaFuncSetAttribute(tc_gemm<MODE, WF32, WHL>,
                             cudaFuncAttributeMaxDynamicSharedMemorySize, SMEM_TOTAL);
        attr_done = true;
    }
    dim3 grid(Npad / 256, B_ROWS / 256);
    tc_gemm<MODE, WF32, WHL><<<grid, 256, SMEM_TOTAL>>>(
        Ahi, Alo, lda, Bhi, Blo, ldb, bias, addhi, addlo, ldadd, sub, ldsub,
        C, ldc, Chi, Clo, ldchl, Nreal, K);
}

extern "C" void kernel_launch(void* const* d_in, const int* in_sizes, int n_in,
                              void* d_out, int out_size)
{
    const float* t          = (const float*)d_in[0];
    const float* state      = (const float*)d_in[1];
    const float* W0         = (const float*)d_in[2];
    const float* b0         = (const float*)d_in[3];
    const float* res_W1     = (const float*)d_in[4];
    const float* res_b1     = (const float*)d_in[5];
    const float* res_W2     = (const float*)d_in[6];
    const float* res_b2     = (const float*)d_in[7];
    const float* Wf         = (const float*)d_in[8];
    const float* bf         = (const float*)d_in[9];
    const float* lp_in_w    = (const float*)d_in[10];
    const float* lp_in_b    = (const float*)d_in[11];
    const float* lp_out_w   = (const float*)d_in[12];
    const float* lp_out_b   = (const float*)d_in[13];
    const float* ta_in_w    = (const float*)d_in[14];
    const float* ta_in_b    = (const float*)d_in[15];
    const float* ta_out_w   = (const float*)d_in[16];
    const float* ta_out_b   = (const float*)d_in[17];
    const float* loc_proj_w = (const float*)d_in[18];
    const float* loc_proj_b = (const float*)d_in[19];
    const float* loc_back_w = (const float*)d_in[20];
    const float* loc_back_b = (const float*)d_in[21];
    float* out = (float*)d_out;

    float* pbeff;
    cudaGetSymbolAddress((void**)&pbeff, g_beff);
    __nv_bfloat16 *p_st_hi, *p_st_lo, *p_w0_hi, *p_w0_lo, *p_h_hi, *p_h_lo,
        *p_u_hi, *p_u_lo, *p_r1_hi, *p_r1_lo, *p_r2_hi, *p_r2_lo,
        *p_wf_hi, *p_wf_lo, *p_tain_hi, *p_tain_lo, *p_taout_hi, *p_taout_lo,
        *p_v2_hi, *p_v2_lo;
    cudaGetSymbolAddress((void**)&p_st_hi, g_state_hi);
    cudaGetSymbolAddress((void**)&p_st_lo, g_state_lo);
    cudaGetSymbolAddress((void**)&p_w0_hi, g_w0_hi);
    cudaGetSymbolAddress((void**)&p_w0_lo, g_w0_lo);
    cudaGetSymbolAddress((void**)&p_h_hi, g_h_hi);
    cudaGetSymbolAddress((void**)&p_h_lo, g_h_lo);
    cudaGetSymbolAddress((void**)&p_u_hi, g_u_hi);
    cudaGetSymbolAddress((void**)&p_u_lo, g_u_lo);
    cudaGetSymbolAddress((void**)&p_r1_hi, g_r1_hi);
    cudaGetSymbolAddress((void**)&p_r1_lo, g_r1_lo);
    cudaGetSymbolAddress((void**)&p_r2_hi, g_r2_hi);
    cudaGetSymbolAddress((void**)&p_r2_lo, g_r2_lo);
    cudaGetSymbolAddress((void**)&p_wf_hi, g_wf_hi);
    cudaGetSymbolAddress((void**)&p_wf_lo, g_wf_lo);
    cudaGetSymbolAddress((void**)&p_tain_hi, g_tain_hi);
    cudaGetSymbolAddress((void**)&p_tain_lo, g_tain_lo);
    cudaGetSymbolAddress((void**)&p_taout_hi, g_taout_hi);
    cudaGetSymbolAddress((void**)&p_taout_lo, g_taout_lo);
    cudaGetSymbolAddress((void**)&p_v2_hi, g_v2_hi);
    cudaGetSymbolAddress((void**)&p_v2_lo, g_v2_lo);

    // ---- ONE fused prep launch ----
    prep_all<<<(PREP_TOTAL + 255) / 256, 256>>>(
        t, b0, state, W0, res_W1, res_W2, Wf,
        ta_in_w + (size_t)2 * A_DIM * A_DIM, ta_out_w);

    // ---- GEMM 0: h = relu(state @ W0^T + beff) -> h hi/lo ----
    launch_tc<1, false, true>(p_st_hi, p_st_lo, SP_DIM, p_w0_hi, p_w0_lo, SP_DIM,
                              pbeff, nullptr, nullptr, 0, nullptr, 0,
                              nullptr, 0, p_h_hi, p_h_lo, H_DIM, H_DIM, H_DIM, SP_DIM);

    // ---- 8 residual blocks ----
    for (int r = 0; r < 8; r++) {
        const __nv_bfloat16* W1h = p_r1_hi + (size_t)r * H_DIM * H_DIM;
        const __nv_bfloat16* W1l = p_r1_lo + (size_t)r * H_DIM * H_DIM;
        const __nv_bfloat16* W2h = p_r2_hi + (size_t)r * H_DIM * H_DIM;
        const __nv_bfloat16* W2l = p_r2_lo + (size_t)r * H_DIM * H_DIM;
        const float* b1 = res_b1 + (size_t)r * H_DIM;
        const float* b2 = res_b2 + (size_t)r * H_DIM;
        launch_tc<2, false, true>(p_h_hi, p_h_lo, H_DIM, W1h, W1l, H_DIM,
                                  b1, nullptr, nullptr, 0, nullptr, 0,
                                  nullptr, 0, p_u_hi, p_u_lo, H_DIM, H_DIM, H_DIM, H_DIM);
        launch_tc<3, false, true>(p_u_hi, p_u_lo, H_DIM, W2h, W2l, H_DIM,
                                  b2, p_h_hi, p_h_lo, H_DIM, nullptr, 0,
                                  nullptr, 0, p_h_hi, p_h_lo, H_DIM, H_DIM, H_DIM, H_DIM);
    }

    // ---- core = h @ Wf^T + bf -> out ----
    launch_tc<0, true, false>(p_h_hi, p_h_lo, H_DIM, p_wf_hi, p_wf_lo, H_DIM,
                              bf, nullptr, nullptr, 0, nullptr, 0,
                              out, S_DIM, nullptr, nullptr, 0, NF_PAD, S_DIM, H_DIM);

    // ---- v2 = state[:, :256] @ ta_in_w[2A:]^T + b -> v2_hl ----
    launch_tc<0, false, true>(p_st_hi, p_st_lo, SP_DIM, p_tain_hi, p_tain_lo, A_DIM,
                              ta_in_b + 2 * A_DIM, nullptr, nullptr, 0, nullptr, 0,
                              nullptr, 0, p_v2_hi, p_v2_lo, A_DIM, A_DIM, A_DIM, A_DIM);

    // ---- out[:, :256] += 0.1 * (v2 @ ta_out_w^T + b - h_part) ----
    launch_tc<4, true, false>(p_v2_hi, p_v2_lo, A_DIM, p_taout_hi, p_taout_lo, A_DIM,
                              ta_out_b, nullptr, nullptr, 0, state, S_DIM,
                              out, S_DIM, nullptr, nullptr, 0, A_DIM, A_DIM, A_DIM);

    // ---- loc path ----
    loc_final_kernel<<<(B_ROWS + 255) / 256, 256>>>(
        state, lp_in_w, lp_in_b, lp_out_w, lp_out_b,
        loc_proj_w, loc_proj_b, loc_back_w, loc_back_b, out);
}

// round 13
// speedup vs baseline: 1.1621x; 1.0165x over previous
#include <cuda_runtime.h>
#include <cuda.h>
#include <cuda_bf16.h>
#include <cstdint>
#include <math.h>

#define B_ROWS 8192
#define S_DIM  268
#define SP_DIM 320
#define H_DIM  1024
#define A_DIM  256
#define NF_PAD 512

#if defined(__CUDA_ARCH__) && defined(__CUDA_ARCH_FEAT_SM103_ALL)
#define TC_ENABLED 1
#else
#define TC_ENABLED 0
#endif

#define STG_STRIDE 260

#define TILE_BYTES 16384    // one operand tile: 256 rows x 64B (K=32 bf16, SW64)
#define STAGE_BYTES (4 * TILE_BYTES)
#define NSTAGES 3
#define SMEM_TOTAL (NSTAGES * STAGE_BYTES)   // 196608

// ---------------- scratch ----------------
__device__ float g_beff[H_DIM];
__device__ __nv_bfloat16 g_state_hi[B_ROWS * SP_DIM];
__device__ __nv_bfloat16 g_state_lo[B_ROWS * SP_DIM];
__device__ __nv_bfloat16 g_w0_hi[H_DIM * SP_DIM];
__device__ __nv_bfloat16 g_w0_lo[H_DIM * SP_DIM];
__device__ __nv_bfloat16 g_h_hi[B_ROWS * H_DIM];
__device__ __nv_bfloat16 g_h_lo[B_ROWS * H_DIM];
__device__ __nv_bfloat16 g_u_hi[B_ROWS * H_DIM];
__device__ __nv_bfloat16 g_u_lo[B_ROWS * H_DIM];
__device__ __nv_bfloat16 g_r1_hi[8 * H_DIM * H_DIM];
__device__ __nv_bfloat16 g_r1_lo[8 * H_DIM * H_DIM];
__device__ __nv_bfloat16 g_r2_hi[8 * H_DIM * H_DIM];
__device__ __nv_bfloat16 g_r2_lo[8 * H_DIM * H_DIM];
__device__ __nv_bfloat16 g_wf_hi[NF_PAD * H_DIM];
__device__ __nv_bfloat16 g_wf_lo[NF_PAD * H_DIM];
__device__ __nv_bfloat16 g_tain_hi[A_DIM * A_DIM];
__device__ __nv_bfloat16 g_tain_lo[A_DIM * A_DIM];
__device__ __nv_bfloat16 g_taout_hi[A_DIM * A_DIM];
__device__ __nv_bfloat16 g_taout_lo[A_DIM * A_DIM];
__device__ __nv_bfloat16 g_v2_hi[B_ROWS * A_DIM];
__device__ __nv_bfloat16 g_v2_lo[B_ROWS * A_DIM];

// ---------------- ptx helpers ----------------
__device__ __forceinline__ uint32_t smem_u32(const void* p) {
    uint32_t a;
    asm("{ .reg .u64 t; cvta.to.shared.u64 t, %1; cvt.u32.u64 %0, t; }" : "=r"(a) : "l"(p));
    return a;
}
__device__ __forceinline__ bool elect_one() {
    uint32_t pred;
    asm volatile("{\n\t.reg .pred p;\n\telect.sync _|p, 0xFFFFFFFF;\n\tselp.b32 %0, 1, 0, p;\n\t}"
                 : "=r"(pred));
    return pred != 0;
}
__device__ __forceinline__ void mbar_init(uint32_t addr, uint32_t cnt) {
    asm volatile("mbarrier.init.shared.b64 [%0], %1;" :: "r"(addr), "r"(cnt) : "memory");
}
__device__ __forceinline__ void mbar_expect_tx(uint32_t addr, uint32_t bytes) {
    asm volatile("mbarrier.arrive.expect_tx.shared.b64 _, [%0], %1;"
                 :: "r"(addr), "r"(bytes) : "memory");
}
__device__ __forceinline__ void mbar_wait(uint32_t addr, uint32_t parity) {
    asm volatile(
        "{\n\t.reg .pred P;\n"
        "WL_%=:\n\t"
        "mbarrier.try_wait.parity.acquire.cta.shared::cta.b64 P, [%0], %1, 0x989680;\n\t"
        "@P bra WD_%=;\n\t"
        "bra WL_%=;\n"
        "WD_%=:\n\t}"
        :: "r"(addr), "r"(parity) : "memory");
}

#if TC_ENABLED
__device__ __forceinline__ void tma_load3d(uint32_t dst, const CUtensorMap* tm,
                                           int x, int y, int z, uint32_t mbar) {
    asm volatile(
        "cp.async.bulk.tensor.3d.shared::cta.global.tile.mbarrier::complete_tx::bytes "
        "[%0], [%1, {%2, %3, %4}], [%5];"
        :: "r"(dst), "l"(tm), "r"(x), "r"(y), "r"(z), "r"(mbar) : "memory");
}
__device__ __forceinline__ void tc_alloc(uint32_t smem_dst, uint32_t ncols) {
    asm volatile("tcgen05.alloc.cta_group::1.sync.aligned.shared::cta.b32 [%0], %1;"
                 :: "r"(smem_dst), "r"(ncols) : "memory");
    asm volatile("tcgen05.relinquish_alloc_permit.cta_group::1.sync.aligned;");
}
__device__ __forceinline__ void tc_dealloc(uint32_t tmem, uint32_t ncols) {
    asm volatile("tcgen05.dealloc.cta_group::1.sync.aligned.b32 %0, %1;"
                 :: "r"(tmem), "r"(ncols));
}
__device__ __forceinline__ void tc_commit(uint32_t mbar) {
    asm volatile("tcgen05.commit.cta_group::1.mbarrier::arrive::one.shared::cluster.b64 [%0];"
                 :: "r"(mbar) : "memory");
}
__device__ __forceinline__ void tc_mma_f16_ss(uint32_t d, uint64_t ad, uint64_t bd,
                                              uint32_t idesc, uint32_t en) {
    asm volatile(
        "{\n\t.reg .pred p;\n\tsetp.ne.u32 p, %4, 0;\n\t"
        "tcgen05.mma.cta_group::1.kind::f16 [%0], %1, %2, %3, p;\n\t}"
        :: "r"(d), "l"(ad), "l"(bd), "r"(idesc), "r"(en) : "memory");
}
__device__ __forceinline__ void tc_fence_after() {
    asm volatile("tcgen05.fence::after_thread_sync;" ::: "memory");
}
__device__ __forceinline__ void tc_fence_before() {
    asm volatile("tcgen05.fence::before_thread_sync;" ::: "memory");
}
__device__ __forceinline__ void tc_ld32_nw(uint32_t* regs, uint32_t addr) {
    asm volatile(
        "tcgen05.ld.sync.aligned.32x32b.x32.b32 "
        "{%0, %1, %2, %3, %4, %5, %6, %7, %8, %9, %10, %11, %12, %13, %14, %15, "
        " %16, %17, %18, %19, %20, %21, %22, %23, %24, %25, %26, %27, %28, %29, %30, %31}, [%32];"
        : "=r"(regs[0]),  "=r"(regs[1]),  "=r"(regs[2]),  "=r"(regs[3]),
          "=r"(regs[4]),  "=r"(regs[5]),  "=r"(regs[6]),  "=r"(regs[7]),
          "=r"(regs[8]),  "=r"(regs[9]),  "=r"(regs[10]), "=r"(regs[11]),
          "=r"(regs[12]), "=r"(regs[13]), "=r"(regs[14]), "=r"(regs[15]),
          "=r"(regs[16]), "=r"(regs[17]), "=r"(regs[18]), "=r"(regs[19]),
          "=r"(regs[20]), "=r"(regs[21]), "=r"(regs[22]), "=r"(regs[23]),
          "=r"(regs[24]), "=r"(regs[25]), "=r"(regs[26]), "=r"(regs[27]),
          "=r"(regs[28]), "=r"(regs[29]), "=r"(regs[30]), "=r"(regs[31])
        : "r"(addr));
}
__device__ __forceinline__ void tc_wait_ld() {
    asm volatile("tcgen05.wait::ld.sync.aligned;" ::: "memory");
}
#endif

// SW64 K-major descriptor: layout=4, SBO=32, LBO=1
static constexpr uint64_t DESC_BASE_SW64 =
    (4ull << 61) | (1ull << 46) | (32ull << 32) | (1ull << 16);
__device__ __forceinline__ uint64_t make_desc64(uint32_t a) {
    return DESC_BASE_SW64 | (uint64_t)((a >> 4) & 0x3FFF);
}

// idesc: F32 accum, BF16 a/b, N=256, M=128
#define TC_IDESC (0x490u | (32u << 17) | (8u << 24))

// ---------------- fused prep ----------------
__device__ __forceinline__ void conv4_store(float4 v, __nv_bfloat16* hi,
                                            __nv_bfloat16* lo, size_t e) {
    __nv_bfloat16 h0 = __float2bfloat16(v.x), h1 = __float2bfloat16(v.y);
    __nv_bfloat16 h2 = __float2bfloat16(v.z), h3 = __float2bfloat16(v.w);
    __nv_bfloat162* hp = (__nv_bfloat162*)(hi + e);
    hp[0] = __nv_bfloat162(h0, h1);
    hp[1] = __nv_bfloat162(h2, h3);
    __nv_bfloat162* lp = (__nv_bfloat162*)(lo + e);
    lp[0] = __nv_bfloat162(__float2bfloat16(v.x - __bfloat162float(h0)),
                           __float2bfloat16(v.y - __bfloat162float(h1)));
    lp[1] = __nv_bfloat162(__float2bfloat16(v.z - __bfloat162float(h2)),
                           __float2bfloat16(v.w - __bfloat162float(h3)));
}

#define N_STATE (B_ROWS * SP_DIM / 4)
#define N_W0    (H_DIM * SP_DIM / 4)
#define N_R     (8 * H_DIM * H_DIM / 4)
#define N_WF    (NF_PAD * H_DIM / 4)
#define N_TA    (A_DIM * A_DIM / 4)
#define PREP_TOTAL (N_STATE + N_W0 + 2 * N_R + N_WF + 2 * N_TA + H_DIM)

__global__ void prep_all(const float* __restrict__ t, const float* __restrict__ b0,
                         const float* __restrict__ state, const float* __restrict__ W0,
                         const float* __restrict__ r1, const float* __restrict__ r2,
                         const float* __restrict__ wf,
                         const float* __restrict__ tain, const float* __restrict__ taout) {
    int i = blockIdx.x * blockDim.x + threadIdx.x;
    if (i < N_STATE) {
        int e = i * 4;
        int r = e / SP_DIM, c0 = e - r * SP_DIM;
        float4 v;
        float* vp = (float*)&v;
#pragma unroll
        for (int k = 0; k < 4; k++) {
            int c = c0 + k;
            vp[k] = (c < S_DIM) ? state[(size_t)r * S_DIM + c] : 0.0f;
        }
        conv4_store(v, g_state_hi, g_state_lo, (size_t)e);
        return;
    }
    i -= N_STATE;
    if (i < N_W0) {
        int e = i * 4;
        int r = e / SP_DIM, c0 = e - r * SP_DIM;
        float4 v;
        float* vp = (float*)&v;
#pragma unroll
        for (int k = 0; k < 4; k++) {
            int c = c0 + k;
            vp[k] = (c < S_DIM) ? W0[(size_t)r * 270 + c] : 0.0f;
        }
        conv4_store(v, g_w0_hi, g_w0_lo, (size_t)e);
        return;
    }
    i -= N_W0;
    if (i < N_R) { conv4_store(((const float4*)r1)[i], g_r1_hi, g_r1_lo, (size_t)i * 4); return; }
    i -= N_R;
    if (i < N_R) { conv4_store(((const float4*)r2)[i], g_r2_hi, g_r2_lo, (size_t)i * 4); return; }
    i -= N_R;
    if (i < N_WF) {
        int e = i * 4;
        int r = e / H_DIM;
        float4 v = (r < S_DIM) ? ((const float4*)wf)[i] : make_float4(0.f, 0.f, 0.f, 0.f);
        conv4_store(v, g_wf_hi, g_wf_lo, (size_t)e);
        return;
    }
    i -= N_WF;
    if (i < N_TA) { conv4_store(((const float4*)tain)[i], g_tain_hi, g_tain_lo, (size_t)i * 4); return; }
    i -= N_TA;
    if (i < N_TA) { conv4_store(((const float4*)taout)[i], g_taout_hi, g_taout_lo, (size_t)i * 4); return; }
    i -= N_TA;
    if (i < H_DIM) {
        float ang = t[0] * (float)(2.0 * M_PI / 24.0);
        float s, c;
        sincosf(ang, &s, &c);
        g_beff[i] = b0[i] + s * W0[i * 270 + 268] + c * W0[i * 270 + 269];
    }
}

// ---------------- GEMM: C = epi(A @ B^T + bias) ----------------
// 256x256 tile; TMA bulk loads (SW64) with one producer thread + one MMA thread.
template <int MODE, bool WF32, bool WHL>
__global__ void __launch_bounds__(256, 1)
tc_gemm(const __grid_constant__ CUtensorMap tmAh, const __grid_constant__ CUtensorMap tmAl,
        const __grid_constant__ CUtensorMap tmBh, const __grid_constant__ CUtensorMap tmBl,
        int zB,
        const __nv_bfloat16* __restrict__ Ahi, const __nv_bfloat16* __restrict__ Alo, int lda,
        const __nv_bfloat16* __restrict__ Bhi, const __nv_bfloat16* __restrict__ Blo, int ldb,
        const float* __restrict__ bias,
        const __nv_bfloat16* __restrict__ addhi, const __nv_bfloat16* __restrict__ addlo, int ldadd,
        const float* __restrict__ sub, int ldsub,
        float* __restrict__ C, int ldc,
        __nv_bfloat16* __restrict__ Chi, __nv_bfloat16* __restrict__ Clo, int ldchl,
        int Nreal, int K)
{
#if TC_ENABLED
    extern __shared__ __align__(1024) char smem[];
    __shared__ __align__(8) uint64_t s_full[NSTAGES];
    __shared__ __align__(8) uint64_t s_empty[NSTAGES];
    __shared__ uint32_t s_tmemptr;

    const int tid = threadIdx.x;
    const int wid = tid >> 5;
    const int lid = tid & 31;
    const int block_row = blockIdx.y * 256;
    const int block_col = blockIdx.x * 256;

    uint32_t fb[NSTAGES], eb[NSTAGES];
#pragma unroll
    for (int s = 0; s < NSTAGES; s++) {
        fb[s] = smem_u32(&s_full[s]);
        eb[s] = smem_u32(&s_empty[s]);
    }
    if (tid == 0) {
#pragma unroll
        for (int s = 0; s < NSTAGES; s++) {
            mbar_init(fb[s], 1);
            mbar_init(eb[s], 1);
        }
    }
    if (wid == 0) tc_alloc(smem_u32(&s_tmemptr), 512u);
    __syncthreads();
    const uint32_t tmem = s_tmemptr;
    const uint32_t sbase = smem_u32(smem);
    const int nchunks = K / 32;

    if (wid == 1 && elect_one()) {
        // ---------------- TMA producer ----------------
        uint32_t pe[NSTAGES] = {0, 0, 0};
        for (int c = 0; c < nchunks; c++) {
            const int s = c % NSTAGES;
            if (c >= NSTAGES) {
                mbar_wait(eb[s], pe[s]);
                pe[s] ^= 1;
            }
            mbar_expect_tx(fb[s], STAGE_BYTES);
            const int k0 = c * 32;
            const uint32_t b = sbase + (uint32_t)s * STAGE_BYTES;
            tma_load3d(b,                  &tmAh, k0, block_row, 0,  fb[s]);
            tma_load3d(b + TILE_BYTES,     &tmAl, k0, block_row, 0,  fb[s]);
            tma_load3d(b + 2 * TILE_BYTES, &tmBh, k0, block_col, zB, fb[s]);
            tma_load3d(b + 3 * TILE_BYTES, &tmBl, k0, block_col, zB, fb[s]);
        }
    } else if (wid == 0 && elect_one()) {
        // ---------------- MMA issuer ----------------
        uint32_t pf[NSTAGES] = {0, 0, 0};
        for (int c = 0; c < nchunks; c++) {
            const int s = c % NSTAGES;
            mbar_wait(fb[s], pf[s]);
            pf[s] ^= 1;
            uint32_t b = sbase + (uint32_t)s * STAGE_BYTES;
            uint64_t dAh = make_desc64(b);
            uint64_t dAl = make_desc64(b + TILE_BYTES);
            uint64_t dBh = make_desc64(b + 2 * TILE_BYTES);
            uint64_t dBl = make_desc64(b + 3 * TILE_BYTES);
#pragma unroll
            for (int ks = 0; ks < 2; ks++) {
                uint64_t o = (uint64_t)(ks * 2);    // 32B per K=16 step
#pragma unroll
                for (int half = 0; half < 2; half++) {
                    uint32_t d = tmem + half * 256;
                    uint64_t ha = (uint64_t)(half * 512);  // 128 rows * 64B / 16
                    uint32_t en0 = (c > 0 || ks > 0) ? 1u : 0u;
                    tc_mma_f16_ss(d, dAh + ha + o, dBh + o, TC_IDESC, en0);
                    tc_mma_f16_ss(d, dAh + ha + o, dBl + o, TC_IDESC, 1);
                    tc_mma_f16_ss(d, dAl + ha + o, dBh + o, TC_IDESC, 1);
                }
            }
            tc_commit(eb[s]);
        }
        const int sl = (nchunks - 1) % NSTAGES;
        const int uses = (nchunks - 1) / NSTAGES + 1;
        mbar_wait(eb[sl], (uint32_t)((uses - 1) & 1));
    }
    __syncthreads();          // gates epilogue on issuer's final wait
    tc_fence_after();

    // ---- epilogue: two M halves; 8 warps column-split ----
    float* stage = (float*)smem;
    const int wq = wid & 3;
    const int colh = (wid >= 4) ? 128 : 0;
    const int cgrp = tid & 63;
    const int rgrp = tid >> 6;
    const int gcol = block_col + cgrp * 4;
    const bool colok = (gcol < Nreal);

    for (int half = 0; half < 2; half++) {
        const int r = wq * 32 + lid;
#pragma unroll
        for (int b = 0; b < 4; b += 2) {
            uint32_t regs0[32], regs1[32];
            tc_ld32_nw(regs0, tmem + half * 256 + colh + b * 32);
            tc_ld32_nw(regs1, tmem + half * 256 + colh + (b + 1) * 32);
            tc_wait_ld();
#pragma unroll
            for (int j = 0; j < 32; j++) {
                stage[r * STG_STRIDE + colh + b * 32 + j] = __uint_as_float(regs0[j]);
                stage[r * STG_STRIDE + colh + (b + 1) * 32 + j] = __uint_as_float(regs1[j]);
            }
        }
        __syncthreads();

        for (int rr = 0; rr < 32; rr++) {
            int r2 = rgrp * 32 + rr;
            int grow = block_row + half * 128 + r2;
            float4 v = *(const float4*)&stage[r2 * STG_STRIDE + cgrp * 4];
            if (colok) {
                float4 bb = *(const float4*)(bias + gcol);
                float f[4] = {v.x + bb.x, v.y + bb.y, v.z + bb.z, v.w + bb.w};
                if (MODE == 1) {
#pragma unroll
                    for (int k = 0; k < 4; k++) f[k] = fmaxf(f[k], 0.0f);
                } else if (MODE == 2) {
#pragma unroll
                    for (int k = 0; k < 4; k++) f[k] = tanhf(f[k]);
                } else if (MODE == 3) {
                    const __nv_bfloat162* ah = (const __nv_bfloat162*)(addhi + (size_t)grow * ldadd + gcol);
                    const __nv_bfloat162* al = (const __nv_bfloat162*)(addlo + (size_t)grow * ldadd + gcol);
                    float2 h01 = __bfloat1622float2(ah[0]), h23 = __bfloat1622float2(ah[1]);
                    float2 l01 = __bfloat1622float2(al[0]), l23 = __bfloat1622float2(al[1]);
                    f[0] = tanhf(f[0] + h01.x + l01.x);
                    f[1] = tanhf(f[1] + h01.y + l01.y);
                    f[2] = tanhf(f[2] + h23.x + l23.x);
                    f[3] = tanhf(f[3] + h23.y + l23.y);
                } else if (MODE == 4) {
                    float4 s4 = *(const float4*)(sub + (size_t)grow * ldsub + gcol);
                    float4 c4 = *(const float4*)(C + (size_t)grow * ldc + gcol);
                    f[0] = c4.x + 0.1f * (f[0] - s4.x);
                    f[1] = c4.y + 0.1f * (f[1] - s4.y);
                    f[2] = c4.z + 0.1f * (f[2] - s4.z);
                    f[3] = c4.w + 0.1f * (f[3] - s4.w);
                }
                if (WF32 || MODE == 4) {
                    float4 o4 = {f[0], f[1], f[2], f[3]};
                    *(float4*)(C + (size_t)grow * ldc + gcol) = o4;
                }
                if (WHL) {
                    __nv_bfloat16 h0 = __float2bfloat16(f[0]), h1 = __float2bfloat16(f[1]);
                    __nv_bfloat16 h2 = __float2bfloat16(f[2]), h3 = __float2bfloat16(f[3]);
                    __nv_bfloat162* hp = (__nv_bfloat162*)(Chi + (size_t)grow * ldchl + gcol);
                    hp[0] = __nv_bfloat162(h0, h1);
                    hp[1] = __nv_bfloat162(h2, h3);
                    __nv_bfloat162* lp = (__nv_bfloat162*)(Clo + (size_t)grow * ldchl + gcol);
                    lp[0] = __nv_bfloat162(__float2bfloat16(f[0] - __bfloat162float(h0)),
                                           __float2bfloat16(f[1] - __bfloat162float(h1)));
                    lp[1] = __nv_bfloat162(__float2bfloat16(f[2] - __bfloat162float(h2)),
                                           __float2bfloat16(f[3] - __bfloat162float(h3)));
                }
            }
        }
        __syncthreads();
    }
    tc_fence_before();
    if (wid == 0) tc_dealloc(tmem, 512u);
#else
    // scalar fallback for the non-sm_103a PTX pass (never selected at runtime)
    const int tid = threadIdx.x;
    const int block_row = blockIdx.y * 256;
    const int block_col = blockIdx.x * 256;
    const int row = block_row + tid;
    const __nv_bfloat16* Bh = Bhi + (size_t)zB * H_DIM * H_DIM;
    const __nv_bfloat16* Bl = Blo + (size_t)zB * H_DIM * H_DIM;
    for (int j = 0; j < 256; j++) {
        int col = block_col + j;
        if (col >= Nreal) continue;
        float acc = 0.0f;
        for (int k = 0; k < K; k++) {
            float a = __bfloat162float(Ahi[(size_t)row * lda + k]) +
                      __bfloat162float(Alo[(size_t)row * lda + k]);
            float w = __bfloat162float(Bh[(size_t)col * ldb + k]) +
                      __bfloat162float(Bl[(size_t)col * ldb + k]);
            acc = fmaf(a, w, acc);
        }
        float v = acc + bias[col];
        float f;
        if (MODE == 0) f = v;
        else if (MODE == 1) f = fmaxf(v, 0.0f);
        else if (MODE == 2) f = tanhf(v);
        else if (MODE == 3) {
            float av = __bfloat162float(addhi[(size_t)row * ldadd + col]) +
                       __bfloat162float(addlo[(size_t)row * ldadd + col]);
            f = tanhf(av + v);
        } else {
            f = C[(size_t)row * ldc + col] + 0.1f * (v - sub[(size_t)row * ldsub + col]);
        }
        if (WF32 || MODE == 4) C[(size_t)row * ldc + col] = f;
        if (WHL) {
            __nv_bfloat16 h = __float2bfloat16(f);
            Chi[(size_t)row * ldchl + col] = h;
            Clo[(size_t)row * ldchl + col] = __float2bfloat16(f - __bfloat162float(h));
        }
    }
#endif
}

// ---------------- tiny per-row loc path ----------------
__global__ void loc_final_kernel(const float* __restrict__ state,
                                 const float* __restrict__ lp_in_w, const float* __restrict__ lp_in_b,
                                 const float* __restrict__ lp_out_w, const float* __restrict__ lp_out_b,
                                 const float* __restrict__ loc_proj_w, const float* __restrict__ loc_proj_b,
                                 const float* __restrict__ loc_back_w, const float* __restrict__ loc_back_b,
                                 float* __restrict__ out)
{
    int m = blockIdx.x * blockDim.x + threadIdx.x;
    if (m >= B_ROWS) return;
    float loc[8];
#pragma unroll
    for (int z = 0; z < 8; z++) loc[z] = state[(size_t)m * S_DIM + A_DIM + z];
    float locp[4];
#pragma unroll
    for (int e = 0; e < 4; e++) {
        float s = loc_proj_b[e];
#pragma unroll
        for (int z = 0; z < 8; z++) s = fmaf(loc_proj_w[e * 8 + z], loc[z], s);
        locp[e] = s;
    }
    float v[4];
#pragma unroll
    for (int e = 0; e < 4; e++) {
        float s = lp_in_b[8 + e];
#pragma unroll
        for (int j = 0; j < 4; j++) s = fmaf(lp_in_w[(8 + e) * 4 + j], locp[j], s);
        v[e] = s;
    }
    float enh[4];
#pragma unroll
    for (int e = 0; e < 4; e++) {
        float s = lp_out_b[e];
#pragma unroll
        for (int j = 0; j < 4; j++) s = fmaf(lp_out_w[e * 4 + j], v[j], s);
        enh[e] = s - locp[e];
    }
#pragma unroll
    for (int z = 0; z < 8; z++) {
        float s = loc_back_b[z];
#pragma unroll
        for (int e = 0; e < 4; e++) s = fmaf(loc_back_w[z * 4 + e], enh[e], s);
        out[(size_t)m * S_DIM + A_DIM + z] += 0.1f * s;
    }
}

// ---------------- host ----------------
// cudaTypedefs.h isn't available in this TU; declare the driver entry type ourselves.
typedef CUresult (CUDAAPI *tm_encode_fn_t)(
    CUtensorMap* tensorMap, CUtensorMapDataType tensorDataType, cuuint32_t tensorRank,
    void* globalAddress, const cuuint64_t* globalDim, const cuuint64_t* globalStrides,
    const cuuint32_t* boxDim, const cuuint32_t* elementStrides,
    CUtensorMapInterleave interleave, CUtensorMapSwizzle swizzle,
    CUtensorMapL2promotion l2Promotion, CUtensorMapFloatOOBfill oobFill);

static tm_encode_fn_t get_encoder() {
    static tm_encode_fn_t fn = nullptr;
    if (!fn) {
        cudaDriverEntryPointQueryResult st;
#if CUDART_VERSION >= 12050
        cudaGetDriverEntryPointByVersion("cuTensorMapEncodeTiled", (void**)&fn, 12000,
                                         cudaEnableDefault, &st);
#else
        cudaGetDriverEntryPoint("cuTensorMapEncodeTiled", (void**)&fn, cudaEnableDefault, &st);
#endif
    }
    return fn;
}

static void enc_tm(CUtensorMap* tm, const void* ptr, uint64_t kdim, uint64_t rows, uint64_t nz) {
    cuuint64_t dims[3] = {kdim, rows, nz};
    cuuint64_t strides[2] = {kdim * 2, kdim * rows * 2};
    cuuint32_t box[3] = {32, 256, 1};
    cuuint32_t estr[3] = {1, 1, 1};
    get_encoder()(tm, CU_TENSOR_MAP_DATA_TYPE_BFLOAT16, 3, (void*)ptr,
                  dims, strides, box, estr,
                  CU_TENSOR_MAP_INTERLEAVE_NONE, CU_TENSOR_MAP_SWIZZLE_64B,
                  CU_TENSOR_MAP_L2_PROMOTION_L2_128B, CU_TENSOR_MAP_FLOAT_OOB_FILL_NONE);
}

template <int MODE, bool WF32, bool WHL>
static void launch_tc(const CUtensorMap& tAh, const CUtensorMap& tAl,
                      const CUtensorMap& tBh, const CUtensorMap& tBl, int zB,
                      const __nv_bfloat16* Ahi, const __nv_bfloat16* Alo, int lda,
                      const __nv_bfloat16* Bhi, const __nv_bfloat16* Blo, int ldb,
                      const float* bias,
                      const __nv_bfloat16* addhi, const __nv_bfloat16* addlo, int ldadd,
                      const float* sub, int ldsub,
                      float* C, int ldc,
                      __nv_bfloat16* Chi, __nv_bfloat16* Clo, int ldchl,
                      int Npad, int Nreal, int K)
{
    static bool attr_done = false;
    if (!attr_done) {
        cudaFuncSetAttribute(tc_gemm<MODE, WF32, WHL>,
                             cudaFuncAttributeMaxDynamicSharedMemorySize, SMEM_TOTAL);
        attr_done = true;
    }
    dim3 grid(Npad / 256, B_ROWS / 256);
    tc_gemm<MODE, WF32, WHL><<<grid, 256, SMEM_TOTAL>>>(
        tAh, tAl, tBh, tBl, zB,
        Ahi, Alo, lda, Bhi, Blo, ldb, bias, addhi, addlo, ldadd, sub, ldsub,
        C, ldc, Chi, Clo, ldchl, Nreal, K);
}

extern "C" void kernel_launch(void* const* d_in, const int* in_sizes, int n_in,
                              void* d_out, int out_size)
{
    const float* t          = (const float*)d_in[0];
    const float* state      = (const float*)d_in[1];
    const float* W0         = (const float*)d_in[2];
    const float* b0         = (const float*)d_in[3];
    const float* res_W1     = (const float*)d_in[4];
    const float* res_b1     = (const float*)d_in[5];
    const float* res_W2     = (const float*)d_in[6];
    const float* res_b2     = (const float*)d_in[7];
    const float* Wf         = (const float*)d_in[8];
    const float* bf         = (const float*)d_in[9];
    const float* lp_in_w    = (const float*)d_in[10];
    const float* lp_in_b    = (const float*)d_in[11];
    const float* lp_out_w   = (const float*)d_in[12];
    const float* lp_out_b   = (const float*)d_in[13];
    const float* ta_in_w    = (const float*)d_in[14];
    const float* ta_in_b    = (const float*)d_in[15];
    const float* ta_out_w   = (const float*)d_in[16];
    const float* ta_out_b   = (const float*)d_in[17];
    const float* loc_proj_w = (const float*)d_in[18];
    const float* loc_proj_b = (const float*)d_in[19];
    const float* loc_back_w = (const float*)d_in[20];
    const float* loc_back_b = (const float*)d_in[21];
    float* out = (float*)d_out;

    float* pbeff;
    cudaGetSymbolAddress((void**)&pbeff, g_beff);
    __nv_bfloat16 *p_st_hi, *p_st_lo, *p_w0_hi, *p_w0_lo, *p_h_hi, *p_h_lo,
        *p_u_hi, *p_u_lo, *p_r1_hi, *p_r1_lo, *p_r2_hi, *p_r2_lo,
        *p_wf_hi, *p_wf_lo, *p_tain_hi, *p_tain_lo, *p_taout_hi, *p_taout_lo,
        *p_v2_hi, *p_v2_lo;
    cudaGetSymbolAddress((void**)&p_st_hi, g_state_hi);
    cudaGetSymbolAddress((void**)&p_st_lo, g_state_lo);
    cudaGetSymbolAddress((void**)&p_w0_hi, g_w0_hi);
    cudaGetSymbolAddress((void**)&p_w0_lo, g_w0_lo);
    cudaGetSymbolAddress((void**)&p_h_hi, g_h_hi);
    cudaGetSymbolAddress((void**)&p_h_lo, g_h_lo);
    cudaGetSymbolAddress((void**)&p_u_hi, g_u_hi);
    cudaGetSymbolAddress((void**)&p_u_lo, g_u_lo);
    cudaGetSymbolAddress((void**)&p_r1_hi, g_r1_hi);
    cudaGetSymbolAddress((void**)&p_r1_lo, g_r1_lo);
    cudaGetSymbolAddress((void**)&p_r2_hi, g_r2_hi);
    cudaGetSymbolAddress((void**)&p_r2_lo, g_r2_lo);
    cudaGetSymbolAddress((void**)&p_wf_hi, g_wf_hi);
    cudaGetSymbolAddress((void**)&p_wf_lo, g_wf_lo);
    cudaGetSymbolAddress((void**)&p_tain_hi, g_tain_hi);
    cudaGetSymbolAddress((void**)&p_tain_lo, g_tain_lo);
    cudaGetSymbolAddress((void**)&p_taout_hi, g_taout_hi);
    cudaGetSymbolAddress((void**)&p_taout_lo, g_taout_lo);
    cudaGetSymbolAddress((void**)&p_v2_hi, g_v2_hi);
    cudaGetSymbolAddress((void**)&p_v2_lo, g_v2_lo);

    // ---- tensormaps (host-side encode; runs during capture only) ----
    CUtensorMap t_st_h, t_st_l, t_w0_h, t_w0_l, t_h_h, t_h_l, t_u_h, t_u_l,
        t_r1_h, t_r1_l, t_r2_h, t_r2_l, t_wf_h, t_wf_l,
        t_ti_h, t_ti_l, t_to_h, t_to_l, t_v2_h, t_v2_l;
    enc_tm(&t_st_h, p_st_hi, SP_DIM, B_ROWS, 1);
    enc_tm(&t_st_l, p_st_lo, SP_DIM, B_ROWS, 1);
    enc_tm(&t_w0_h, p_w0_hi, SP_DIM, H_DIM, 1);
    enc_tm(&t_w0_l, p_w0_lo, SP_DIM, H_DIM, 1);
    enc_tm(&t_h_h, p_h_hi, H_DIM, B_ROWS, 1);
    enc_tm(&t_h_l, p_h_lo, H_DIM, B_ROWS, 1);
    enc_tm(&t_u_h, p_u_hi, H_DIM, B_ROWS, 1);
    enc_tm(&t_u_l, p_u_lo, H_DIM, B_ROWS, 1);
    enc_tm(&t_r1_h, p_r1_hi, H_DIM, H_DIM, 8);
    enc_tm(&t_r1_l, p_r1_lo, H_DIM, H_DIM, 8);
    enc_tm(&t_r2_h, p_r2_hi, H_DIM, H_DIM, 8);
    enc_tm(&t_r2_l, p_r2_lo, H_DIM, H_DIM, 8);
    enc_tm(&t_wf_h, p_wf_hi, H_DIM, NF_PAD, 1);
    enc_tm(&t_wf_l, p_wf_lo, H_DIM, NF_PAD, 1);
    enc_tm(&t_ti_h, p_tain_hi, A_DIM, A_DIM, 1);
    enc_tm(&t_ti_l, p_tain_lo, A_DIM, A_DIM, 1);
    enc_tm(&t_to_h, p_taout_hi, A_DIM, A_DIM, 1);
    enc_tm(&t_to_l, p_taout_lo, A_DIM, A_DIM, 1);
    enc_tm(&t_v2_h, p_v2_hi, A_DIM, B_ROWS, 1);
    enc_tm(&t_v2_l, p_v2_lo, A_DIM, B_ROWS, 1);

    // ---- ONE fused prep launch ----
    prep_all<<<(PREP_TOTAL + 255) / 256, 256>>>(
        t, b0, state, W0, res_W1, res_W2, Wf,
        ta_in_w + (size_t)2 * A_DIM * A_DIM, ta_out_w);

    // ---- GEMM 0: h = relu(state @ W0^T + beff) -> h hi/lo ----
    launch_tc<1, false, true>(t_st_h, t_st_l, t_w0_h, t_w0_l, 0,
                              p_st_hi, p_st_lo, SP_DIM, p_w0_hi, p_w0_lo, SP_DIM,
                              pbeff, nullptr, nullptr, 0, nullptr, 0,
                              nullptr, 0, p_h_hi, p_h_lo, H_DIM, H_DIM, H_DIM, SP_DIM);

    // ---- 8 residual blocks ----
    for (int r = 0; r < 8; r++) {
        const float* b1 = res_b1 + (size_t)r * H_DIM;
        const float* b2 = res_b2 + (size_t)r * H_DIM;
        // u = tanh(h @ W1^T + b1)
        launch_tc<2, false, true>(t_h_h, t_h_l, t_r1_h, t_r1_l, r,
                                  p_h_hi, p_h_lo, H_DIM, p_r1_hi, p_r1_lo, H_DIM,
                                  b1, nullptr, nullptr, 0, nullptr, 0,
                                  nullptr, 0, p_u_hi, p_u_lo, H_DIM, H_DIM, H_DIM, H_DIM);
        // h = tanh(h + u @ W2^T + b2)
        launch_tc<3, false, true>(t_u_h, t_u_l, t_r2_h, t_r2_l, r,
                                  p_u_hi, p_u_lo, H_DIM, p_r2_hi, p_r2_lo, H_DIM,
                                  b2, p_h_hi, p_h_lo, H_DIM, nullptr, 0,
                                  nullptr, 0, p_h_hi, p_h_lo, H_DIM, H_DIM, H_DIM, H_DIM);
    }

    // ---- core = h @ Wf^T + bf -> out ----
    launch_tc<0, true, false>(t_h_h, t_h_l, t_wf_h, t_wf_l, 0,
                              p_h_hi, p_h_lo, H_DIM, p_wf_hi, p_wf_lo, H_DIM,
                              bf, nullptr, nullptr, 0, nullptr, 0,
                              out, S_DIM, nullptr, nullptr, 0, NF_PAD, S_DIM, H_DIM);

    // ---- v2 = state[:, :256] @ ta_in_w[2A:]^T + b ----
    launch_tc<0, false, true>(t_st_h, t_st_l, t_ti_h, t_ti_l, 0,
                              p_st_hi, p_st_lo, SP_DIM, p_tain_hi, p_tain_lo, A_DIM,
                              ta_in_b + 2 * A_DIM, nullptr, nullptr, 0, nullptr, 0,
                              nullptr, 0, p_v2_hi, p_v2_lo, A_DIM, A_DIM, A_DIM, A_DIM);

    // ---- out[:, :256] += 0.1 * (v2 @ ta_out_w^T + b - h_part) ----
    launch_tc<4, true, false>(t_v2_h, t_v2_l, t_to_h, t_to_l, 0,
                              p_v2_hi, p_v2_lo, A_DIM, p_taout_hi, p_taout_lo, A_DIM,
                              ta_out_b, nullptr, nullptr, 0, state, S_DIM,
                              out, S_DIM, nullptr, nullptr, 0, A_DIM, A_DIM, A_DIM);

    // ---- loc path ----
    loc_final_kernel<<<(B_ROWS + 255) / 256, 256>>>(
        state, lp_in_w, lp_in_b, lp_out_w, lp_out_b,
        loc_proj_w, loc_proj_b, loc_back_w, loc_back_b, out);
}

// round 14
// speedup vs baseline: 1.3899x; 1.1960x over previous
#include <cuda_runtime.h>
#include <cuda.h>
#include <cuda_bf16.h>
#include <cstdint>
#include <math.h>

#define B_ROWS 8192
#define S_DIM  268
#define SP_DIM 320
#define H_DIM  1024
#define A_DIM  256
#define NF_PAD 512

#if defined(__CUDA_ARCH__) && defined(__CUDA_ARCH_FEAT_SM103_ALL)
#define TC_ENABLED 1
#else
#define TC_ENABLED 0
#endif

#define STG_STRIDE 132      // floats; %4==0

// CTA tile 128x256, K chunk 32 (SW64 tiles, 64B rows)
#define A_TILE_BYTES 8192    // 128 rows x 64B
#define B_TILE_BYTES 16384   // 256 rows x 64B
#define STAGE_BYTES (2 * A_TILE_BYTES + 2 * B_TILE_BYTES)   // 48KB
#define NSTAGES 2
#define SMEM_TOTAL (NSTAGES * STAGE_BYTES)   // 98304 -> 2 CTAs/SM

// ---------------- scratch ----------------
__device__ float g_beff[H_DIM];
__device__ __nv_bfloat16 g_state_hi[B_ROWS * SP_DIM];
__device__ __nv_bfloat16 g_state_lo[B_ROWS * SP_DIM];
__device__ __nv_bfloat16 g_w0_hi[H_DIM * SP_DIM];
__device__ __nv_bfloat16 g_w0_lo[H_DIM * SP_DIM];
__device__ __nv_bfloat16 g_h_hi[B_ROWS * H_DIM];
__device__ __nv_bfloat16 g_h_lo[B_ROWS * H_DIM];
__device__ __nv_bfloat16 g_u_hi[B_ROWS * H_DIM];
__device__ __nv_bfloat16 g_u_lo[B_ROWS * H_DIM];
__device__ __nv_bfloat16 g_r1_hi[8 * H_DIM * H_DIM];
__device__ __nv_bfloat16 g_r1_lo[8 * H_DIM * H_DIM];
__device__ __nv_bfloat16 g_r2_hi[8 * H_DIM * H_DIM];
__device__ __nv_bfloat16 g_r2_lo[8 * H_DIM * H_DIM];
__device__ __nv_bfloat16 g_wf_hi[NF_PAD * H_DIM];
__device__ __nv_bfloat16 g_wf_lo[NF_PAD * H_DIM];
__device__ __nv_bfloat16 g_tain_hi[A_DIM * A_DIM];
__device__ __nv_bfloat16 g_tain_lo[A_DIM * A_DIM];
__device__ __nv_bfloat16 g_taout_hi[A_DIM * A_DIM];
__device__ __nv_bfloat16 g_taout_lo[A_DIM * A_DIM];
__device__ __nv_bfloat16 g_v2_hi[B_ROWS * A_DIM];
__device__ __nv_bfloat16 g_v2_lo[B_ROWS * A_DIM];

// ---------------- ptx helpers ----------------
__device__ __forceinline__ uint32_t smem_u32(const void* p) {
    uint32_t a;
    asm("{ .reg .u64 t; cvta.to.shared.u64 t, %1; cvt.u32.u64 %0, t; }" : "=r"(a) : "l"(p));
    return a;
}
__device__ __forceinline__ bool elect_one() {
    uint32_t pred;
    asm volatile("{\n\t.reg .pred p;\n\telect.sync _|p, 0xFFFFFFFF;\n\tselp.b32 %0, 1, 0, p;\n\t}"
                 : "=r"(pred));
    return pred != 0;
}
__device__ __forceinline__ void mbar_init(uint32_t addr, uint32_t cnt) {
    asm volatile("mbarrier.init.shared.b64 [%0], %1;" :: "r"(addr), "r"(cnt) : "memory");
}
__device__ __forceinline__ void mbar_expect_tx(uint32_t addr, uint32_t bytes) {
    asm volatile("mbarrier.arrive.expect_tx.shared.b64 _, [%0], %1;"
                 :: "r"(addr), "r"(bytes) : "memory");
}
__device__ __forceinline__ void mbar_wait(uint32_t addr, uint32_t parity) {
    asm volatile(
        "{\n\t.reg .pred P;\n"
        "WL_%=:\n\t"
        "mbarrier.try_wait.parity.acquire.cta.shared::cta.b64 P, [%0], %1, 0x989680;\n\t"
        "@P bra WD_%=;\n\t"
        "bra WL_%=;\n"
        "WD_%=:\n\t}"
        :: "r"(addr), "r"(parity) : "memory");
}

#if TC_ENABLED
__device__ __forceinline__ void tma_load3d(uint32_t dst, const CUtensorMap* tm,
                                           int x, int y, int z, uint32_t mbar) {
    asm volatile(
        "cp.async.bulk.tensor.3d.shared::cta.global.tile.mbarrier::complete_tx::bytes "
        "[%0], [%1, {%2, %3, %4}], [%5];"
        :: "r"(dst), "l"(tm), "r"(x), "r"(y), "r"(z), "r"(mbar) : "memory");
}
__device__ __forceinline__ void tc_alloc(uint32_t smem_dst, uint32_t ncols) {
    asm volatile("tcgen05.alloc.cta_group::1.sync.aligned.shared::cta.b32 [%0], %1;"
                 :: "r"(smem_dst), "r"(ncols) : "memory");
    asm volatile("tcgen05.relinquish_alloc_permit.cta_group::1.sync.aligned;");
}
__device__ __forceinline__ void tc_dealloc(uint32_t tmem, uint32_t ncols) {
    asm volatile("tcgen05.dealloc.cta_group::1.sync.aligned.b32 %0, %1;"
                 :: "r"(tmem), "r"(ncols));
}
__device__ __forceinline__ void tc_commit(uint32_t mbar) {
    asm volatile("tcgen05.commit.cta_group::1.mbarrier::arrive::one.shared::cluster.b64 [%0];"
                 :: "r"(mbar) : "memory");
}
__device__ __forceinline__ void tc_mma_f16_ss(uint32_t d, uint64_t ad, uint64_t bd,
                                              uint32_t idesc, uint32_t en) {
    asm volatile(
        "{\n\t.reg .pred p;\n\tsetp.ne.u32 p, %4, 0;\n\t"
        "tcgen05.mma.cta_group::1.kind::f16 [%0], %1, %2, %3, p;\n\t}"
        :: "r"(d), "l"(ad), "l"(bd), "r"(idesc), "r"(en) : "memory");
}
__device__ __forceinline__ void tc_fence_after() {
    asm volatile("tcgen05.fence::after_thread_sync;" ::: "memory");
}
__device__ __forceinline__ void tc_fence_before() {
    asm volatile("tcgen05.fence::before_thread_sync;" ::: "memory");
}
__device__ __forceinline__ void tc_ld32_nw(uint32_t* regs, uint32_t addr) {
    asm volatile(
        "tcgen05.ld.sync.aligned.32x32b.x32.b32 "
        "{%0, %1, %2, %3, %4, %5, %6, %7, %8, %9, %10, %11, %12, %13, %14, %15, "
        " %16, %17, %18, %19, %20, %21, %22, %23, %24, %25, %26, %27, %28, %29, %30, %31}, [%32];"
        : "=r"(regs[0]),  "=r"(regs[1]),  "=r"(regs[2]),  "=r"(regs[3]),
          "=r"(regs[4]),  "=r"(regs[5]),  "=r"(regs[6]),  "=r"(regs[7]),
          "=r"(regs[8]),  "=r"(regs[9]),  "=r"(regs[10]), "=r"(regs[11]),
          "=r"(regs[12]), "=r"(regs[13]), "=r"(regs[14]), "=r"(regs[15]),
          "=r"(regs[16]), "=r"(regs[17]), "=r"(regs[18]), "=r"(regs[19]),
          "=r"(regs[20]), "=r"(regs[21]), "=r"(regs[22]), "=r"(regs[23]),
          "=r"(regs[24]), "=r"(regs[25]), "=r"(regs[26]), "=r"(regs[27]),
          "=r"(regs[28]), "=r"(regs[29]), "=r"(regs[30]), "=r"(regs[31])
        : "r"(addr));
}
__device__ __forceinline__ void tc_wait_ld() {
    asm volatile("tcgen05.wait::ld.sync.aligned;" ::: "memory");
}
#endif

// SW64 K-major descriptor: layout=4, SBO=32, LBO=1
static constexpr uint64_t DESC_BASE_SW64 =
    (4ull << 61) | (1ull << 46) | (32ull << 32) | (1ull << 16);
__device__ __forceinline__ uint64_t make_desc64(uint32_t a) {
    return DESC_BASE_SW64 | (uint64_t)((a >> 4) & 0x3FFF);
}

// idesc: F32 accum, BF16 a/b, N=256, M=128
#define TC_IDESC (0x490u | (32u << 17) | (8u << 24))

// ---------------- fused prep ----------------
__device__ __forceinline__ void conv4_store(float4 v, __nv_bfloat16* hi,
                                            __nv_bfloat16* lo, size_t e) {
    __nv_bfloat16 h0 = __float2bfloat16(v.x), h1 = __float2bfloat16(v.y);
    __nv_bfloat16 h2 = __float2bfloat16(v.z), h3 = __float2bfloat16(v.w);
    __nv_bfloat162* hp = (__nv_bfloat162*)(hi + e);
    hp[0] = __nv_bfloat162(h0, h1);
    hp[1] = __nv_bfloat162(h2, h3);
    __nv_bfloat162* lp = (__nv_bfloat162*)(lo + e);
    lp[0] = __nv_bfloat162(__float2bfloat16(v.x - __bfloat162float(h0)),
                           __float2bfloat16(v.y - __bfloat162float(h1)));
    lp[1] = __nv_bfloat162(__float2bfloat16(v.z - __bfloat162float(h2)),
                           __float2bfloat16(v.w - __bfloat162float(h3)));
}

#define N_STATE (B_ROWS * SP_DIM / 4)
#define N_W0    (H_DIM * SP_DIM / 4)
#define N_R     (8 * H_DIM * H_DIM / 4)
#define N_WF    (NF_PAD * H_DIM / 4)
#define N_TA    (A_DIM * A_DIM / 4)
#define PREP_TOTAL (N_STATE + N_W0 + 2 * N_R + N_WF + 2 * N_TA + H_DIM)

__global__ void prep_all(const float* __restrict__ t, const float* __restrict__ b0,
                         const float* __restrict__ state, const float* __restrict__ W0,
                         const float* __restrict__ r1, const float* __restrict__ r2,
                         const float* __restrict__ wf,
                         const float* __restrict__ tain, const float* __restrict__ taout) {
    int i = blockIdx.x * blockDim.x + threadIdx.x;
    if (i < N_STATE) {
        int e = i * 4;
        int r = e / SP_DIM, c0 = e - r * SP_DIM;
        float4 v;
        float* vp = (float*)&v;
#pragma unroll
        for (int k = 0; k < 4; k++) {
            int c = c0 + k;
            vp[k] = (c < S_DIM) ? state[(size_t)r * S_DIM + c] : 0.0f;
        }
        conv4_store(v, g_state_hi, g_state_lo, (size_t)e);
        return;
    }
    i -= N_STATE;
    if (i < N_W0) {
        int e = i * 4;
        int r = e / SP_DIM, c0 = e - r * SP_DIM;
        float4 v;
        float* vp = (float*)&v;
#pragma unroll
        for (int k = 0; k < 4; k++) {
            int c = c0 + k;
            vp[k] = (c < S_DIM) ? W0[(size_t)r * 270 + c] : 0.0f;
        }
        conv4_store(v, g_w0_hi, g_w0_lo, (size_t)e);
        return;
    }
    i -= N_W0;
    if (i < N_R) { conv4_store(((const float4*)r1)[i], g_r1_hi, g_r1_lo, (size_t)i * 4); return; }
    i -= N_R;
    if (i < N_R) { conv4_store(((const float4*)r2)[i], g_r2_hi, g_r2_lo, (size_t)i * 4); return; }
    i -= N_R;
    if (i < N_WF) {
        int e = i * 4;
        int r = e / H_DIM;
        float4 v = (r < S_DIM) ? ((const float4*)wf)[i] : make_float4(0.f, 0.f, 0.f, 0.f);
        conv4_store(v, g_wf_hi, g_wf_lo, (size_t)e);
        return;
    }
    i -= N_WF;
    if (i < N_TA) { conv4_store(((const float4*)tain)[i], g_tain_hi, g_tain_lo, (size_t)i * 4); return; }
    i -= N_TA;
    if (i < N_TA) { conv4_store(((const float4*)taout)[i], g_taout_hi, g_taout_lo, (size_t)i * 4); return; }
    i -= N_TA;
    if (i < H_DIM) {
        float ang = t[0] * (float)(2.0 * M_PI / 24.0);
        float s, c;
        sincosf(ang, &s, &c);
        g_beff[i] = b0[i] + s * W0[i * 270 + 268] + c * W0[i * 270 + 269];
    }
}

// ---------------- GEMM: C = epi(A @ B^T + bias) ----------------
// 128x256 tile, 2 CTAs/SM; TMA producer thread + MMA issuer thread; 2 stages.
template <int MODE, bool WF32, bool WHL>
__global__ void __launch_bounds__(256, 2)
tc_gemm(const __grid_constant__ CUtensorMap tmAh, const __grid_constant__ CUtensorMap tmAl,
        const __grid_constant__ CUtensorMap tmBh, const __grid_constant__ CUtensorMap tmBl,
        int zB,
        const __nv_bfloat16* __restrict__ Ahi, const __nv_bfloat16* __restrict__ Alo, int lda,
        const __nv_bfloat16* __restrict__ Bhi, const __nv_bfloat16* __restrict__ Blo, int ldb,
        const float* __restrict__ bias,
        const __nv_bfloat16* __restrict__ addhi, const __nv_bfloat16* __restrict__ addlo, int ldadd,
        const float* __restrict__ sub, int ldsub,
        float* __restrict__ C, int ldc,
        __nv_bfloat16* __restrict__ Chi, __nv_bfloat16* __restrict__ Clo, int ldchl,
        int Nreal, int K)
{
#if TC_ENABLED
    extern __shared__ __align__(1024) char smem[];
    __shared__ __align__(8) uint64_t s_full[NSTAGES];
    __shared__ __align__(8) uint64_t s_empty[NSTAGES];
    __shared__ uint32_t s_tmemptr;

    const int tid = threadIdx.x;
    const int wid = tid >> 5;
    const int lid = tid & 31;
    const int block_row = blockIdx.y * 128;
    const int block_col = blockIdx.x * 256;

    uint32_t fb[NSTAGES], eb[NSTAGES];
#pragma unroll
    for (int s = 0; s < NSTAGES; s++) {
        fb[s] = smem_u32(&s_full[s]);
        eb[s] = smem_u32(&s_empty[s]);
    }
    if (tid == 0) {
#pragma unroll
        for (int s = 0; s < NSTAGES; s++) {
            mbar_init(fb[s], 1);
            mbar_init(eb[s], 1);
        }
    }
    if (wid == 0) tc_alloc(smem_u32(&s_tmemptr), 256u);
    __syncthreads();
    const uint32_t tmem = s_tmemptr;
    const uint32_t sbase = smem_u32(smem);
    const int nchunks = K / 32;

    if (wid == 1 && elect_one()) {
        // ---------------- TMA producer ----------------
        uint32_t pe[NSTAGES] = {0, 0};
        for (int c = 0; c < nchunks; c++) {
            const int s = c & 1;
            if (c >= NSTAGES) {
                mbar_wait(eb[s], pe[s]);
                pe[s] ^= 1;
            }
            mbar_expect_tx(fb[s], STAGE_BYTES);
            const int k0 = c * 32;
            const uint32_t b = sbase + (uint32_t)s * STAGE_BYTES;
            tma_load3d(b,                    &tmAh, k0, block_row, 0,  fb[s]);
            tma_load3d(b + A_TILE_BYTES,     &tmAl, k0, block_row, 0,  fb[s]);
            tma_load3d(b + 2 * A_TILE_BYTES, &tmBh, k0, block_col, zB, fb[s]);
            tma_load3d(b + 2 * A_TILE_BYTES + B_TILE_BYTES, &tmBl, k0, block_col, zB, fb[s]);
        }
    } else if (wid == 0 && elect_one()) {
        // ---------------- MMA issuer ----------------
        uint32_t pf[NSTAGES] = {0, 0};
        for (int c = 0; c < nchunks; c++) {
            const int s = c & 1;
            mbar_wait(fb[s], pf[s]);
            pf[s] ^= 1;
            uint32_t b = sbase + (uint32_t)s * STAGE_BYTES;
            uint64_t dAh = make_desc64(b);
            uint64_t dAl = make_desc64(b + A_TILE_BYTES);
            uint64_t dBh = make_desc64(b + 2 * A_TILE_BYTES);
            uint64_t dBl = make_desc64(b + 2 * A_TILE_BYTES + B_TILE_BYTES);
#pragma unroll
            for (int ks = 0; ks < 2; ks++) {
                uint64_t o = (uint64_t)(ks * 2);    // 32B per K=16 step
                uint32_t en0 = (c > 0 || ks > 0) ? 1u : 0u;
                tc_mma_f16_ss(tmem, dAh + o, dBh + o, TC_IDESC, en0);
                tc_mma_f16_ss(tmem, dAh + o, dBl + o, TC_IDESC, 1);
                tc_mma_f16_ss(tmem, dAl + o, dBh + o, TC_IDESC, 1);
            }
            tc_commit(eb[s]);
        }
        const int sl = (nchunks - 1) & 1;
        const int uses = (nchunks - 1) / NSTAGES + 1;
        mbar_wait(eb[sl], (uint32_t)((uses - 1) & 1));
    }
    __syncthreads();          // gates epilogue on issuer's final wait
    tc_fence_after();

    // ---- epilogue: two 128-col halves through 128x132 staging ----
    float* stage = (float*)smem;
    const int sp = wid & 3;                  // subpartition rows sp*32..+31
    const int cg = wid >> 2;                 // 64-col group within half
    const int ccol = (tid & 31) * 4;
    const int rgrp = tid >> 5;               // 8 groups x 16 rows

    for (int half = 0; half < 2; half++) {
        const int r = sp * 32 + lid;
#pragma unroll
        for (int b = 0; b < 2; b++) {
            uint32_t regs[32];
            tc_ld32_nw(regs, tmem + half * 128 + cg * 64 + b * 32);
            tc_wait_ld();
#pragma unroll
            for (int j = 0; j < 32; j++)
                stage[r * STG_STRIDE + cg * 64 + b * 32 + j] = __uint_as_float(regs[j]);
        }
        __syncthreads();

        const int gcol = block_col + half * 128 + ccol;
        const bool colok = (gcol < Nreal);     // Nreal % 4 == 0
        for (int rr = 0; rr < 16; rr++) {
            int r2 = rgrp * 16 + rr;
            int grow = block_row + r2;
            float4 v = *(const float4*)&stage[r2 * STG_STRIDE + ccol];
            if (colok) {
                float4 bb = *(const float4*)(bias + gcol);
                float f[4] = {v.x + bb.x, v.y + bb.y, v.z + bb.z, v.w + bb.w};
                if (MODE == 1) {
#pragma unroll
                    for (int k = 0; k < 4; k++) f[k] = fmaxf(f[k], 0.0f);
                } else if (MODE == 2) {
#pragma unroll
                    for (int k = 0; k < 4; k++) f[k] = tanhf(f[k]);
                } else if (MODE == 3) {
                    const __nv_bfloat162* ah = (const __nv_bfloat162*)(addhi + (size_t)grow * ldadd + gcol);
                    const __nv_bfloat162* al = (const __nv_bfloat162*)(addlo + (size_t)grow * ldadd + gcol);
                    float2 h01 = __bfloat1622float2(ah[0]), h23 = __bfloat1622float2(ah[1]);
                    float2 l01 = __bfloat1622float2(al[0]), l23 = __bfloat1622float2(al[1]);
                    f[0] = tanhf(f[0] + h01.x + l01.x);
                    f[1] = tanhf(f[1] + h01.y + l01.y);
                    f[2] = tanhf(f[2] + h23.x + l23.x);
                    f[3] = tanhf(f[3] + h23.y + l23.y);
                } else if (MODE == 4) {
                    float4 s4 = *(const float4*)(sub + (size_t)grow * ldsub + gcol);
                    float4 c4 = *(const float4*)(C + (size_t)grow * ldc + gcol);
                    f[0] = c4.x + 0.1f * (f[0] - s4.x);
                    f[1] = c4.y + 0.1f * (f[1] - s4.y);
                    f[2] = c4.z + 0.1f * (f[2] - s4.z);
                    f[3] = c4.w + 0.1f * (f[3] - s4.w);
                }
                if (WF32 || MODE == 4) {
                    float4 o4 = {f[0], f[1], f[2], f[3]};
                    *(float4*)(C + (size_t)grow * ldc + gcol) = o4;
                }
                if (WHL) {
                    __nv_bfloat16 h0 = __float2bfloat16(f[0]), h1 = __float2bfloat16(f[1]);
                    __nv_bfloat16 h2 = __float2bfloat16(f[2]), h3 = __float2bfloat16(f[3]);
                    __nv_bfloat162* hp = (__nv_bfloat162*)(Chi + (size_t)grow * ldchl + gcol);
                    hp[0] = __nv_bfloat162(h0, h1);
                    hp[1] = __nv_bfloat162(h2, h3);
                    __nv_bfloat162* lp = (__nv_bfloat162*)(Clo + (size_t)grow * ldchl + gcol);
                    lp[0] = __nv_bfloat162(__float2bfloat16(f[0] - __bfloat162float(h0)),
                                           __float2bfloat16(f[1] - __bfloat162float(h1)));
                    lp[1] = __nv_bfloat162(__float2bfloat16(f[2] - __bfloat162float(h2)),
                                           __float2bfloat16(f[3] - __bfloat162float(h3)));
                }
            }
        }
        __syncthreads();
    }
    tc_fence_before();
    if (wid == 0) tc_dealloc(tmem, 256u);
#else
    // scalar fallback for the non-sm_103a PTX pass (never selected at runtime)
    const int tid = threadIdx.x;
    if (tid >= 128) return;
    const int block_row = blockIdx.y * 128;
    const int block_col = blockIdx.x * 256;
    const int row = block_row + tid;
    const __nv_bfloat16* Bh = Bhi + (size_t)zB * H_DIM * H_DIM;
    const __nv_bfloat16* Bl = Blo + (size_t)zB * H_DIM * H_DIM;
    for (int j = 0; j < 256; j++) {
        int col = block_col + j;
        if (col >= Nreal) continue;
        float acc = 0.0f;
        for (int k = 0; k < K; k++) {
            float a = __bfloat162float(Ahi[(size_t)row * lda + k]) +
                      __bfloat162float(Alo[(size_t)row * lda + k]);
            float w = __bfloat162float(Bh[(size_t)col * ldb + k]) +
                      __bfloat162float(Bl[(size_t)col * ldb + k]);
            acc = fmaf(a, w, acc);
        }
        float v = acc + bias[col];
        float f;
        if (MODE == 0) f = v;
        else if (MODE == 1) f = fmaxf(v, 0.0f);
        else if (MODE == 2) f = tanhf(v);
        else if (MODE == 3) {
            float av = __bfloat162float(addhi[(size_t)row * ldadd + col]) +
                       __bfloat162float(addlo[(size_t)row * ldadd + col]);
            f = tanhf(av + v);
        } else {
            f = C[(size_t)row * ldc + col] + 0.1f * (v - sub[(size_t)row * ldsub + col]);
        }
        if (WF32 || MODE == 4) C[(size_t)row * ldc + col] = f;
        if (WHL) {
            __nv_bfloat16 h = __float2bfloat16(f);
            Chi[(size_t)row * ldchl + col] = h;
            Clo[(size_t)row * ldchl + col] = __float2bfloat16(f - __bfloat162float(h));
        }
    }
#endif
}

// ---------------- tiny per-row loc path ----------------
__global__ void loc_final_kernel(const float* __restrict__ state,
                                 const float* __restrict__ lp_in_w, const float* __restrict__ lp_in_b,
                                 const float* __restrict__ lp_out_w, const float* __restrict__ lp_out_b,
                                 const float* __restrict__ loc_proj_w, const float* __restrict__ loc_proj_b,
                                 const float* __restrict__ loc_back_w, const float* __restrict__ loc_back_b,
                                 float* __restrict__ out)
{
    int m = blockIdx.x * blockDim.x + threadIdx.x;
    if (m >= B_ROWS) return;
    float loc[8];
#pragma unroll
    for (int z = 0; z < 8; z++) loc[z] = state[(size_t)m * S_DIM + A_DIM + z];
    float locp[4];
#pragma unroll
    for (int e = 0; e < 4; e++) {
        float s = loc_proj_b[e];
#pragma unroll
        for (int z = 0; z < 8; z++) s = fmaf(loc_proj_w[e * 8 + z], loc[z], s);
        locp[e] = s;
    }
    float v[4];
#pragma unroll
    for (int e = 0; e < 4; e++) {
        float s = lp_in_b[8 + e];
#pragma unroll
        for (int j = 0; j < 4; j++) s = fmaf(lp_in_w[(8 + e) * 4 + j], locp[j], s);
        v[e] = s;
    }
    float enh[4];
#pragma unroll
    for (int e = 0; e < 4; e++) {
        float s = lp_out_b[e];
#pragma unroll
        for (int j = 0; j < 4; j++) s = fmaf(lp_out_w[e * 4 + j], v[j], s);
        enh[e] = s - locp[e];
    }
#pragma unroll
    for (int z = 0; z < 8; z++) {
        float s = loc_back_b[z];
#pragma unroll
        for (int e = 0; e < 4; e++) s = fmaf(loc_back_w[z * 4 + e], enh[e], s);
        out[(size_t)m * S_DIM + A_DIM + z] += 0.1f * s;
    }
}

// ---------------- host ----------------
typedef CUresult (CUDAAPI *tm_encode_fn_t)(
    CUtensorMap* tensorMap, CUtensorMapDataType tensorDataType, cuuint32_t tensorRank,
    void* globalAddress, const cuuint64_t* globalDim, const cuuint64_t* globalStrides,
    const cuuint32_t* boxDim, const cuuint32_t* elementStrides,
    CUtensorMapInterleave interleave, CUtensorMapSwizzle swizzle,
    CUtensorMapL2promotion l2Promotion, CUtensorMapFloatOOBfill oobFill);

static tm_encode_fn_t get_encoder() {
    static tm_encode_fn_t fn = nullptr;
    if (!fn) {
        cudaDriverEntryPointQueryResult st;
#if CUDART_VERSION >= 12050
        cudaGetDriverEntryPointByVersion("cuTensorMapEncodeTiled", (void**)&fn, 12000,
                                         cudaEnableDefault, &st);
#else
        cudaGetDriverEntryPoint("cuTensorMapEncodeTiled", (void**)&fn, cudaEnableDefault, &st);
#endif
    }
    return fn;
}

static void enc_tm(CUtensorMap* tm, const void* ptr, uint64_t kdim, uint64_t rows,
                   uint64_t nz, uint32_t box_rows) {
    cuuint64_t dims[3] = {kdim, rows, nz};
    cuuint64_t strides[2] = {kdim * 2, kdim * rows * 2};
    cuuint32_t box[3] = {32, box_rows, 1};
    cuuint32_t estr[3] = {1, 1, 1};
    get_encoder()(tm, CU_TENSOR_MAP_DATA_TYPE_BFLOAT16, 3, (void*)ptr,
                  dims, strides, box, estr,
                  CU_TENSOR_MAP_INTERLEAVE_NONE, CU_TENSOR_MAP_SWIZZLE_64B,
                  CU_TENSOR_MAP_L2_PROMOTION_L2_128B, CU_TENSOR_MAP_FLOAT_OOB_FILL_NONE);
}

template <int MODE, bool WF32, bool WHL>
static void launch_tc(const CUtensorMap& tAh, const CUtensorMap& tAl,
                      const CUtensorMap& tBh, const CUtensorMap& tBl, int zB,
                      const __nv_bfloat16* Ahi, const __nv_bfloat16* Alo, int lda,
                      const __nv_bfloat16* Bhi, const __nv_bfloat16* Blo, int ldb,
                      const float* bias,
                      const __nv_bfloat16* addhi, const __nv_bfloat16* addlo, int ldadd,
                      const float* sub, int ldsub,
                      float* C, int ldc,
                      __nv_bfloat16* Chi, __nv_bfloat16* Clo, int ldchl,
                      int Npad, int Nreal, int K)
{
    static bool attr_done = false;
    if (!attr_done) {
        cudaFuncSetAttribute(tc_gemm<MODE, WF32, WHL>,
                             cudaFuncAttributeMaxDynamicSharedMemorySize, SMEM_TOTAL);
        attr_done = true;
    }
    dim3 grid(Npad / 256, B_ROWS / 128);
    tc_gemm<MODE, WF32, WHL><<<grid, 256, SMEM_TOTAL>>>(
        tAh, tAl, tBh, tBl, zB,
        Ahi, Alo, lda, Bhi, Blo, ldb, bias, addhi, addlo, ldadd, sub, ldsub,
        C, ldc, Chi, Clo, ldchl, Nreal, K);
}

extern "C" void kernel_launch(void* const* d_in, const int* in_sizes, int n_in,
                              void* d_out, int out_size)
{
    const float* t          = (const float*)d_in[0];
    const float* state      = (const float*)d_in[1];
    const float* W0         = (const float*)d_in[2];
    const float* b0         = (const float*)d_in[3];
    const float* res_W1     = (const float*)d_in[4];
    const float* res_b1     = (const float*)d_in[5];
    const float* res_W2     = (const float*)d_in[6];
    const float* res_b2     = (const float*)d_in[7];
    const float* Wf         = (const float*)d_in[8];
    const float* bf         = (const float*)d_in[9];
    const float* lp_in_w    = (const float*)d_in[10];
    const float* lp_in_b    = (const float*)d_in[11];
    const float* lp_out_w   = (const float*)d_in[12];
    const float* lp_out_b   = (const float*)d_in[13];
    const float* ta_in_w    = (const float*)d_in[14];
    const float* ta_in_b    = (const float*)d_in[15];
    const float* ta_out_w   = (const float*)d_in[16];
    const float* ta_out_b   = (const float*)d_in[17];
    const float* loc_proj_w = (const float*)d_in[18];
    const float* loc_proj_b = (const float*)d_in[19];
    const float* loc_back_w = (const float*)d_in[20];
    const float* loc_back_b = (const float*)d_in[21];
    float* out = (float*)d_out;

    float* pbeff;
    cudaGetSymbolAddress((void**)&pbeff, g_beff);
    __nv_bfloat16 *p_st_hi, *p_st_lo, *p_w0_hi, *p_w0_lo, *p_h_hi, *p_h_lo,
        *p_u_hi, *p_u_lo, *p_r1_hi, *p_r1_lo, *p_r2_hi, *p_r2_lo,
        *p_wf_hi, *p_wf_lo, *p_tain_hi, *p_tain_lo, *p_taout_hi, *p_taout_lo,
        *p_v2_hi, *p_v2_lo;
    cudaGetSymbolAddress((void**)&p_st_hi, g_state_hi);
    cudaGetSymbolAddress((void**)&p_st_lo, g_state_lo);
    cudaGetSymbolAddress((void**)&p_w0_hi, g_w0_hi);
    cudaGetSymbolAddress((void**)&p_w0_lo, g_w0_lo);
    cudaGetSymbolAddress((void**)&p_h_hi, g_h_hi);
    cudaGetSymbolAddress((void**)&p_h_lo, g_h_lo);
    cudaGetSymbolAddress((void**)&p_u_hi, g_u_hi);
    cudaGetSymbolAddress((void**)&p_u_lo, g_u_lo);
    cudaGetSymbolAddress((void**)&p_r1_hi, g_r1_hi);
    cudaGetSymbolAddress((void**)&p_r1_lo, g_r1_lo);
    cudaGetSymbolAddress((void**)&p_r2_hi, g_r2_hi);
    cudaGetSymbolAddress((void**)&p_r2_lo, g_r2_lo);
    cudaGetSymbolAddress((void**)&p_wf_hi, g_wf_hi);
    cudaGetSymbolAddress((void**)&p_wf_lo, g_wf_lo);
    cudaGetSymbolAddress((void**)&p_tain_hi, g_tain_hi);
    cudaGetSymbolAddress((void**)&p_tain_lo, g_tain_lo);
    cudaGetSymbolAddress((void**)&p_taout_hi, g_taout_hi);
    cudaGetSymbolAddress((void**)&p_taout_lo, g_taout_lo);
    cudaGetSymbolAddress((void**)&p_v2_hi, g_v2_hi);
    cudaGetSymbolAddress((void**)&p_v2_lo, g_v2_lo);

    // ---- tensormaps: A operands box 128 rows, B operands box 256 rows ----
    CUtensorMap t_st_h, t_st_l, t_w0_h, t_w0_l, t_h_h, t_h_l, t_u_h, t_u_l,
        t_r1_h, t_r1_l, t_r2_h, t_r2_l, t_wf_h, t_wf_l,
        t_ti_h, t_ti_l, t_to_h, t_to_l, t_v2_h, t_v2_l;
    enc_tm(&t_st_h, p_st_hi, SP_DIM, B_ROWS, 1, 128);
    enc_tm(&t_st_l, p_st_lo, SP_DIM, B_ROWS, 1, 128);
    enc_tm(&t_h_h, p_h_hi, H_DIM, B_ROWS, 1, 128);
    enc_tm(&t_h_l, p_h_lo, H_DIM, B_ROWS, 1, 128);
    enc_tm(&t_u_h, p_u_hi, H_DIM, B_ROWS, 1, 128);
    enc_tm(&t_u_l, p_u_lo, H_DIM, B_ROWS, 1, 128);
    enc_tm(&t_v2_h, p_v2_hi, A_DIM, B_ROWS, 1, 128);
    enc_tm(&t_v2_l, p_v2_lo, A_DIM, B_ROWS, 1, 128);
    enc_tm(&t_w0_h, p_w0_hi, SP_DIM, H_DIM, 1, 256);
    enc_tm(&t_w0_l, p_w0_lo, SP_DIM, H_DIM, 1, 256);
    enc_tm(&t_r1_h, p_r1_hi, H_DIM, H_DIM, 8, 256);
    enc_tm(&t_r1_l, p_r1_lo, H_DIM, H_DIM, 8, 256);
    enc_tm(&t_r2_h, p_r2_hi, H_DIM, H_DIM, 8, 256);
    enc_tm(&t_r2_l, p_r2_lo, H_DIM, H_DIM, 8, 256);
    enc_tm(&t_wf_h, p_wf_hi, H_DIM, NF_PAD, 1, 256);
    enc_tm(&t_wf_l, p_wf_lo, H_DIM, NF_PAD, 1, 256);
    enc_tm(&t_ti_h, p_tain_hi, A_DIM, A_DIM, 1, 256);
    enc_tm(&t_ti_l, p_tain_lo, A_DIM, A_DIM, 1, 256);
    enc_tm(&t_to_h, p_taout_hi, A_DIM, A_DIM, 1, 256);
    enc_tm(&t_to_l, p_taout_lo, A_DIM, A_DIM, 1, 256);

    // ---- ONE fused prep launch ----
    prep_all<<<(PREP_TOTAL + 255) / 256, 256>>>(
        t, b0, state, W0, res_W1, res_W2, Wf,
        ta_in_w + (size_t)2 * A_DIM * A_DIM, ta_out_w);

    // ---- GEMM 0: h = relu(state @ W0^T + beff) -> h hi/lo ----
    launch_tc<1, false, true>(t_st_h, t_st_l, t_w0_h, t_w0_l, 0,
                              p_st_hi, p_st_lo, SP_DIM, p_w0_hi, p_w0_lo, SP_DIM,
                              pbeff, nullptr, nullptr, 0, nullptr, 0,
                              nullptr, 0, p_h_hi, p_h_lo, H_DIM, H_DIM, H_DIM, SP_DIM);

    // ---- 8 residual blocks ----
    for (int r = 0; r < 8; r++) {
        const float* b1 = res_b1 + (size_t)r * H_DIM;
        const float* b2 = res_b2 + (size_t)r * H_DIM;
        launch_tc<2, false, true>(t_h_h, t_h_l, t_r1_h, t_r1_l, r,
                                  p_h_hi, p_h_lo, H_DIM, p_r1_hi, p_r1_lo, H_DIM,
                                  b1, nullptr, nullptr, 0, nullptr, 0,
                                  nullptr, 0, p_u_hi, p_u_lo, H_DIM, H_DIM, H_DIM, H_DIM);
        launch_tc<3, false, true>(t_u_h, t_u_l, t_r2_h, t_r2_l, r,
                                  p_u_hi, p_u_lo, H_DIM, p_r2_hi, p_r2_lo, H_DIM,
                                  b2, p_h_hi, p_h_lo, H_DIM, nullptr, 0,
                                  nullptr, 0, p_h_hi, p_h_lo, H_DIM, H_DIM, H_DIM, H_DIM);
    }

    // ---- core = h @ Wf^T + bf -> out ----
    launch_tc<0, true, false>(t_h_h, t_h_l, t_wf_h, t_wf_l, 0,
                              p_h_hi, p_h_lo, H_DIM, p_wf_hi, p_wf_lo, H_DIM,
                              bf, nullptr, nullptr, 0, nullptr, 0,
                              out, S_DIM, nullptr, nullptr, 0, NF_PAD, S_DIM, H_DIM);

    // ---- v2 = state[:, :256] @ ta_in_w[2A:]^T + b ----
    launch_tc<0, false, true>(t_st_h, t_st_l, t_ti_h, t_ti_l, 0,
                              p_st_hi, p_st_lo, SP_DIM, p_tain_hi, p_tain_lo, A_DIM,
                              ta_in_b + 2 * A_DIM, nullptr, nullptr, 0, nullptr, 0,
                              nullptr, 0, p_v2_hi, p_v2_lo, A_DIM, A_DIM, A_DIM, A_DIM);

    // ---- out[:, :256] += 0.1 * (v2 @ ta_out_w^T + b - h_part) ----
    launch_tc<4, true, false>(t_v2_h, t_v2_l, t_to_h, t_to_l, 0,
                              p_v2_hi, p_v2_lo, A_DIM, p_taout_hi, p_taout_lo, A_DIM,
                              ta_out_b, nullptr, nullptr, 0, state, S_DIM,
                              out, S_DIM, nullptr, nullptr, 0, A_DIM, A_DIM, A_DIM);

    // ---- loc path ----
    loc_final_kernel<<<(B_ROWS + 255) / 256, 256>>>(
        state, lp_in_w, lp_in_b, lp_out_w, lp_out_b,
        loc_proj_w, loc_proj_b, loc_back_w, loc_back_b, out);
}